// round 11
// baseline (speedup 1.0000x reference)
#include <cuda_runtime.h>
#include <cuda_bf16.h>
#include <mma.h>
#include <math.h>

using namespace nvcuda;

// ---------------------------------------------------------------------------
// Problem constants
// ---------------------------------------------------------------------------
#define Bv   8
#define Tv   1024
#define Fv   64
#define DMv  256
#define Lv   4
#define DIv  512          // 2*DM
#define Nv   16
#define DCv  4
#define DTRv 16           // DM/16
#define BT   (Bv*Tv)      // 8192
#define NCH  8            // scan chunks
#define CHT  128          // timesteps per chunk

// ---------------------------------------------------------------------------
// Scratch (device globals; no runtime allocation allowed)
// ---------------------------------------------------------------------------
__device__ float g_h  [BT * DMv];
__device__ float g_xz [BT * (2*DIv)];
__device__ float g_xc [BT * DIv];
__device__ float g_dt [BT * DIv];
__device__ float g_BC [BT * (2*Nv)];
__device__ float g_y  [BT * DIv];

__device__ float g_chP[Bv * DIv * Nv * NCH];
__device__ float g_chH[Bv * DIv * Nv * NCH];

// ---------------------------------------------------------------------------
// Tensor-core GEMM, fp32 emulation via 2-term bf16 split.
// Both A and W are fp32 and split hi/lo on the fly while staging to smem.
// C[M,N] = (A + Abias_cols)[M,K] @ W[N,K]^T.
// BM=64, BN=128, BK=32.  256 threads, 8 warps 2(m)x4(n), warp tile 32x32.
// Requires M%64==0, N%128==0, K%32==0.
// ---------------------------------------------------------------------------
#define SPAD 40

__global__ void __launch_bounds__(256, 2)
wgemm_nt_kernel(const float* __restrict__ A, const float* __restrict__ Abias,
                const float* __restrict__ W,
                float* __restrict__ C,
                int M, int N, int K)
{
    __shared__ __align__(16) __nv_bfloat16 Ah[64*SPAD];
    __shared__ __align__(16) __nv_bfloat16 Al[64*SPAD];
    __shared__ __align__(16) __nv_bfloat16 Bh[128*SPAD];
    __shared__ __align__(16) __nv_bfloat16 Bl[128*SPAD];

    const int tid = threadIdx.x;
    const int bm  = blockIdx.y, bn = blockIdx.x;
    const int wid = tid >> 5;
    const int wm  = wid >> 2;
    const int wn  = wid & 3;

    wmma::fragment<wmma::accumulator, 16, 16, 16, float> acc[2][2];
#pragma unroll
    for (int mi = 0; mi < 2; ++mi)
#pragma unroll
        for (int ni = 0; ni < 2; ++ni)
            wmma::fill_fragment(acc[mi][ni], 0.0f);

    for (int k0 = 0; k0 < K; k0 += 32) {
        // ---- stage A (fp32 -> hi/lo, optional bias along K columns) --------
#pragma unroll
        for (int i = 0; i < 2; ++i) {
            const int idx = tid + i * 256;       // 0..511 float4s
            const int row = idx >> 3;            // 8 float4 per 32-float row
            const int kc  = (idx & 7) << 2;
            float4 v = *(const float4*)(A + (size_t)(bm*64 + row) * K + k0 + kc);
            if (Abias) {
                const float4 bb = *(const float4*)(Abias + k0 + kc);
                v.x += bb.x; v.y += bb.y; v.z += bb.z; v.w += bb.w;
            }
            __nv_bfloat16 h0 = __float2bfloat16(v.x);
            __nv_bfloat16 h1 = __float2bfloat16(v.y);
            __nv_bfloat16 h2 = __float2bfloat16(v.z);
            __nv_bfloat16 h3 = __float2bfloat16(v.w);
            __nv_bfloat162 ph0; ph0.x = h0; ph0.y = h1;
            __nv_bfloat162 ph1; ph1.x = h2; ph1.y = h3;
            *(__nv_bfloat162*)(Ah + row*SPAD + kc)     = ph0;
            *(__nv_bfloat162*)(Ah + row*SPAD + kc + 2) = ph1;
            __nv_bfloat162 pl0; pl0.x = __float2bfloat16(v.x - __bfloat162float(h0));
                                pl0.y = __float2bfloat16(v.y - __bfloat162float(h1));
            __nv_bfloat162 pl1; pl1.x = __float2bfloat16(v.z - __bfloat162float(h2));
                                pl1.y = __float2bfloat16(v.w - __bfloat162float(h3));
            *(__nv_bfloat162*)(Al + row*SPAD + kc)     = pl0;
            *(__nv_bfloat162*)(Al + row*SPAD + kc + 2) = pl1;
        }
        // ---- stage W (fp32 -> hi/lo) ----------------------------------------
#pragma unroll
        for (int i = 0; i < 4; ++i) {
            const int idx = tid + i * 256;       // 0..1023 float4s
            const int row = idx >> 3;            // 128 rows
            const int kc  = (idx & 7) << 2;
            const float4 v = *(const float4*)(W + (size_t)(bn*128 + row) * K + k0 + kc);
            __nv_bfloat16 h0 = __float2bfloat16(v.x);
            __nv_bfloat16 h1 = __float2bfloat16(v.y);
            __nv_bfloat16 h2 = __float2bfloat16(v.z);
            __nv_bfloat16 h3 = __float2bfloat16(v.w);
            __nv_bfloat162 ph0; ph0.x = h0; ph0.y = h1;
            __nv_bfloat162 ph1; ph1.x = h2; ph1.y = h3;
            *(__nv_bfloat162*)(Bh + row*SPAD + kc)     = ph0;
            *(__nv_bfloat162*)(Bh + row*SPAD + kc + 2) = ph1;
            __nv_bfloat162 pl0; pl0.x = __float2bfloat16(v.x - __bfloat162float(h0));
                                pl0.y = __float2bfloat16(v.y - __bfloat162float(h1));
            __nv_bfloat162 pl1; pl1.x = __float2bfloat16(v.z - __bfloat162float(h2));
                                pl1.y = __float2bfloat16(v.w - __bfloat162float(h3));
            *(__nv_bfloat162*)(Bl + row*SPAD + kc)     = pl0;
            *(__nv_bfloat162*)(Bl + row*SPAD + kc + 2) = pl1;
        }
        __syncthreads();

#pragma unroll
        for (int ks = 0; ks < 32; ks += 16) {
            wmma::fragment<wmma::matrix_b, 16, 16, 16, __nv_bfloat16, wmma::col_major> bH[2], bL[2];
#pragma unroll
            for (int ni = 0; ni < 2; ++ni) {
                const int rr = wn*32 + ni*16;
                wmma::load_matrix_sync(bH[ni], Bh + rr*SPAD + ks, SPAD);
                wmma::load_matrix_sync(bL[ni], Bl + rr*SPAD + ks, SPAD);
            }
#pragma unroll
            for (int mi = 0; mi < 2; ++mi) {
                wmma::fragment<wmma::matrix_a, 16, 16, 16, __nv_bfloat16, wmma::row_major> aH, aL;
                const int rr = wm*32 + mi*16;
                wmma::load_matrix_sync(aH, Ah + rr*SPAD + ks, SPAD);
                wmma::load_matrix_sync(aL, Al + rr*SPAD + ks, SPAD);
#pragma unroll
                for (int ni = 0; ni < 2; ++ni) {
                    wmma::mma_sync(acc[mi][ni], aH, bH[ni], acc[mi][ni]);
                    wmma::mma_sync(acc[mi][ni], aH, bL[ni], acc[mi][ni]);
                    wmma::mma_sync(acc[mi][ni], aL, bH[ni], acc[mi][ni]);
                }
            }
        }
        __syncthreads();
    }

#pragma unroll
    for (int mi = 0; mi < 2; ++mi)
#pragma unroll
        for (int ni = 0; ni < 2; ++ni) {
            const int rr = bm*64 + wm*32 + mi*16;
            const int cc = bn*128 + wn*32 + ni*16;
            wmma::store_matrix_sync(C + (size_t)rr * N + cc, acc[mi][ni], N,
                                    wmma::mem_row_major);
        }
}

// ---------------------------------------------------------------------------
// Fused middle kernel (R10 version, unchanged).
// ---------------------------------------------------------------------------
__global__ void __launch_bounds__(256)
fused_mid_kernel(const float* __restrict__ conv_w,
                 const float* __restrict__ conv_b,
                 const float* __restrict__ xpw,
                 const float* __restrict__ dtw,
                 const float* __restrict__ dtb)
{
    __shared__ __align__(16) float xc_s  [16][DIv];
    __shared__ __align__(16) float wc_s  [48][68];
    __shared__ __align__(16) float xdbl_s[16][48];

    const int blk = blockIdx.x;
    const int b   = blk >> 6;
    const int t0  = (blk & 63) << 4;
    const int tid = threadIdx.x;

#pragma unroll
    for (int dd = 0; dd < 2; ++dd) {
        const int d = tid + dd * 256;
        const float* xin = g_xz + (size_t)(b * Tv) * (2*DIv) + d;
        const float4 cw4 = *(const float4*)(conv_w + d*4);
        const float  cb  = conv_b[d];
        float x0 = (t0 - 3 >= 0) ? xin[(size_t)(t0-3) * (2*DIv)] : 0.f;
        float x1 = (t0 - 2 >= 0) ? xin[(size_t)(t0-2) * (2*DIv)] : 0.f;
        float x2 = (t0 - 1 >= 0) ? xin[(size_t)(t0-1) * (2*DIv)] : 0.f;
#pragma unroll
        for (int tt = 0; tt < 16; ++tt) {
            const float x3 = xin[(size_t)(t0+tt) * (2*DIv)];
            float s = cw4.x*x0 + cw4.y*x1 + cw4.z*x2 + cw4.w*x3 + cb;
            float sl = s / (1.f + __expf(-s));
            xc_s[tt][d] = sl;
            g_xc[((size_t)(b*Tv + t0 + tt)) * DIv + d] = sl;
            x0 = x1; x1 = x2; x2 = x3;
        }
    }
    __syncthreads();

    const int tt  = tid >> 4;
    const int oth = tid & 15;
    float acc0 = 0.f, acc1 = 0.f, acc2 = 0.f;

    for (int kc = 0; kc < DIv; kc += 64) {
#pragma unroll
        for (int j = 0; j < 3; ++j) {
            const int l4 = tid * 3 + j;
            const int o  = l4 >> 4;
            const int k  = (l4 & 15) << 2;
            *(float4*)&wc_s[o][k] = *(const float4*)(xpw + o*DIv + kc + k);
        }
        __syncthreads();
#pragma unroll
        for (int k = 0; k < 64; k += 4) {
            const float4 xa = *(const float4*)&xc_s[tt][kc + k];
            const float4 w0 = *(const float4*)&wc_s[oth      ][k];
            const float4 w1 = *(const float4*)&wc_s[oth + 16][k];
            const float4 w2 = *(const float4*)&wc_s[oth + 32][k];
            acc0 += xa.x*w0.x + xa.y*w0.y + xa.z*w0.z + xa.w*w0.w;
            acc1 += xa.x*w1.x + xa.y*w1.y + xa.z*w1.z + xa.w*w1.w;
            acc2 += xa.x*w2.x + xa.y*w2.y + xa.z*w2.z + xa.w*w2.w;
        }
        __syncthreads();
    }
    xdbl_s[tt][oth     ] = acc0;
    xdbl_s[tt][oth + 16] = acc1;
    xdbl_s[tt][oth + 32] = acc2;
    __syncthreads();

    {
        int idx = tid;
#pragma unroll
        for (int r = 0; r < 2; ++r, idx += 256) {
            const int tti = idx >> 5, c = idx & 31;
            g_BC[((size_t)(b*Tv + t0 + tti)) * (2*Nv) + c] = xdbl_s[tti][16 + c];
        }
    }

    {
        const int d0 = tid, d1 = tid + 256;
        float w0[16], w1[16];
        *(float4*)&w0[0]  = *(const float4*)(dtw + d0*16 + 0);
        *(float4*)&w0[4]  = *(const float4*)(dtw + d0*16 + 4);
        *(float4*)&w0[8]  = *(const float4*)(dtw + d0*16 + 8);
        *(float4*)&w0[12] = *(const float4*)(dtw + d0*16 + 12);
        *(float4*)&w1[0]  = *(const float4*)(dtw + d1*16 + 0);
        *(float4*)&w1[4]  = *(const float4*)(dtw + d1*16 + 4);
        *(float4*)&w1[8]  = *(const float4*)(dtw + d1*16 + 8);
        *(float4*)&w1[12] = *(const float4*)(dtw + d1*16 + 12);
        const float b0 = dtb[d0], b1 = dtb[d1];

#pragma unroll
        for (int tt2 = 0; tt2 < 16; ++tt2) {
            float xv[16];
            *(float4*)&xv[0]  = *(const float4*)&xdbl_s[tt2][0];
            *(float4*)&xv[4]  = *(const float4*)&xdbl_s[tt2][4];
            *(float4*)&xv[8]  = *(const float4*)&xdbl_s[tt2][8];
            *(float4*)&xv[12] = *(const float4*)&xdbl_s[tt2][12];
            float s0 = b0, s1 = b1;
#pragma unroll
            for (int r = 0; r < 16; ++r) {
                s0 += xv[r] * w0[r];
                s1 += xv[r] * w1[r];
            }
            const float sp0 = fmaxf(s0, 0.f) + log1pf(__expf(-fabsf(s0)));
            const float sp1 = fmaxf(s1, 0.f) + log1pf(__expf(-fabsf(s1)));
            const size_t o = ((size_t)(b*Tv + t0 + tt2)) * DIv;
            g_dt[o + d0] = sp0;
            g_dt[o + d1] = sp1;
        }
    }
}

// ---------------------------------------------------------------------------
// Scan pass 1: per-chunk (P, H) for chunks 0..6 (chunk 7 unused).
// grid (32, 8, 7), 256 threads.
// ---------------------------------------------------------------------------
__global__ void __launch_bounds__(256)
scan_pass1_kernel(const float* __restrict__ A_log)
{
    __shared__ float s_dt[64][16];
    __shared__ float s_u [64][16];
    __shared__ float s_b [64][16];

    const int d0   = blockIdx.x * 16;
    const int b    = blockIdx.y;
    const int ch   = blockIdx.z;
    const int tid  = threadIdx.x;
    const int warp = tid >> 5;
    const int lane = tid & 31;
    const int half = lane >> 4;
    const int n    = lane & 15;
    const int dloc = warp * 2 + half;
    const int d    = d0 + dloc;

    const float a = -__expf(A_log[d * Nv + n]);
    float h = 0.f, P = 1.f;

    for (int sc = 0; sc < 2; ++sc) {
        const int base = b * Tv + ch * CHT + sc * 64;
#pragma unroll
        for (int i = 0; i < 4; ++i) {
            const int idx = tid + i * 256;
            const int tt  = idx >> 4;
            const int dd  = idx & 15;
            s_dt[tt][dd] = g_dt[(size_t)(base + tt) * DIv + d0 + dd];
            s_u [tt][dd] = g_xc[(size_t)(base + tt) * DIv + d0 + dd];
            s_b [tt][dd] = g_BC[(size_t)(base + tt) * (2*Nv) + dd];
        }
        __syncthreads();
#pragma unroll 4
        for (int tt = 0; tt < 64; ++tt) {
            const float dtv = s_dt[tt][dloc];
            const float uv  = s_u [tt][dloc];
            const float bv  = s_b [tt][n];
            const float dA  = __expf(dtv * a);
            h = dA * h + (dtv * uv) * bv;
            P *= dA;
        }
        __syncthreads();
    }

    const size_t o = (((size_t)b * DIv + d) * Nv + n) * NCH + ch;
    g_chP[o] = P;
    g_chH[o] = h;
}

// ---------------------------------------------------------------------------
// Scan pass 2: computes its chunk's seed S(ch) inline from (P,H) of earlier
// chunks, then scans and emits gated y.  grid (32, 8, 8), 256 threads.
// ---------------------------------------------------------------------------
__global__ void __launch_bounds__(256)
scan_pass2_kernel(const float* __restrict__ A_log, const float* __restrict__ Dp)
{
    __shared__ float s_dt[64][16];
    __shared__ float s_u [64][16];
    __shared__ float s_z [64][16];
    __shared__ float s_bc[64][32];

    const int d0   = blockIdx.x * 16;
    const int b    = blockIdx.y;
    const int ch   = blockIdx.z;
    const int tid  = threadIdx.x;
    const int warp = tid >> 5;
    const int lane = tid & 31;
    const int half = lane >> 4;
    const int n    = lane & 15;
    const int dloc = warp * 2 + half;
    const int d    = d0 + dloc;

    const float a     = -__expf(A_log[d * Nv + n]);
    const float dcoef = Dp[d];

    // inline prefix: S(ch) = fold of (P,H) over chunks 0..ch-1
    float h = 0.f;
    {
        const size_t base = (((size_t)b * DIv + d) * Nv + n) * NCH;
        for (int c = 0; c < ch; ++c)
            h = g_chP[base + c] * h + g_chH[base + c];
    }

    for (int sc = 0; sc < 2; ++sc) {
        const int base = b * Tv + ch * CHT + sc * 64;
#pragma unroll
        for (int i = 0; i < 4; ++i) {
            const int idx = tid + i * 256;
            const int tt  = idx >> 4;
            const int dd  = idx & 15;
            s_dt[tt][dd] = g_dt[(size_t)(base + tt) * DIv + d0 + dd];
            s_u [tt][dd] = g_xc[(size_t)(base + tt) * DIv + d0 + dd];
            s_z [tt][dd] = g_xz[(size_t)(base + tt) * (2*DIv) + DIv + d0 + dd];
        }
#pragma unroll
        for (int i = 0; i < 8; ++i) {
            const int idx = tid + i * 256;
            const int tt  = idx >> 5;
            const int c   = idx & 31;
            s_bc[tt][c] = g_BC[(size_t)(base + tt) * (2*Nv) + c];
        }
        __syncthreads();

#pragma unroll 4
        for (int tt = 0; tt < 64; ++tt) {
            const float dtv = s_dt[tt][dloc];
            const float uv  = s_u [tt][dloc];
            const float bv  = s_bc[tt][n];
            const float cv  = s_bc[tt][Nv + n];

            const float dA = __expf(dtv * a);
            h = dA * h + (dtv * uv) * bv;

            float part = h * cv;
            part += __shfl_xor_sync(0xffffffffu, part, 1);
            part += __shfl_xor_sync(0xffffffffu, part, 2);
            part += __shfl_xor_sync(0xffffffffu, part, 4);
            part += __shfl_xor_sync(0xffffffffu, part, 8);

            if (n == 0) {
                const float zv = s_z[tt][dloc];
                float y = part + dcoef * uv;
                y *= zv / (1.f + __expf(-zv));
                g_y[(size_t)(base + tt) * DIv + d] = y;
            }
        }
        __syncthreads();
    }
}

// ---------------------------------------------------------------------------
// Final: LayerNorm(last token) + head.
// ---------------------------------------------------------------------------
__global__ void __launch_bounds__(256)
final_kernel(const float* __restrict__ ln_g, const float* __restrict__ ln_b,
             const float* __restrict__ head_w, const float* __restrict__ head_b,
             float* __restrict__ out)
{
    __shared__ float red[256];
    const int b = blockIdx.x, tid = threadIdx.x;
    const float v = g_h[((size_t)(b * Tv + (Tv - 1))) * DMv + tid];

    red[tid] = v; __syncthreads();
    for (int s = 128; s > 0; s >>= 1) { if (tid < s) red[tid] += red[tid + s]; __syncthreads(); }
    const float mu = red[0] * (1.f / DMv);
    __syncthreads();

    const float dv = v - mu;
    red[tid] = dv * dv; __syncthreads();
    for (int s = 128; s > 0; s >>= 1) { if (tid < s) red[tid] += red[tid + s]; __syncthreads(); }
    const float var = red[0] * (1.f / DMv);
    __syncthreads();

    const float hn = dv * rsqrtf(var + 1e-5f) * ln_g[tid] + ln_b[tid];
    red[tid] = hn * head_w[tid]; __syncthreads();
    for (int s = 128; s > 0; s >>= 1) { if (tid < s) red[tid] += red[tid + s]; __syncthreads(); }
    if (tid == 0) out[b] = red[0] + head_b[0];
}

// ---------------------------------------------------------------------------
// Host launcher
// ---------------------------------------------------------------------------
extern "C" void kernel_launch(void* const* d_in, const int* in_sizes, int n_in,
                              void* d_out, int out_size)
{
    const float* x      = (const float*)d_in[0];
    const float* proj_w = (const float*)d_in[1];
    const float* proj_b = (const float*)d_in[2];
    const float* ipw    = (const float*)d_in[3];
    const float* cw     = (const float*)d_in[4];
    const float* cb     = (const float*)d_in[5];
    const float* xpw    = (const float*)d_in[6];
    const float* dtw    = (const float*)d_in[7];
    const float* dtb    = (const float*)d_in[8];
    const float* A_log  = (const float*)d_in[9];
    const float* Dp     = (const float*)d_in[10];
    const float* opw    = (const float*)d_in[11];
    const float* ln_g   = (const float*)d_in[12];
    const float* ln_b   = (const float*)d_in[13];
    const float* head_w = (const float*)d_in[14];
    const float* head_b = (const float*)d_in[15];
    float* out = (float*)d_out;

    float *hbuf, *xzbuf, *ybuf;
    cudaGetSymbolAddress((void**)&hbuf,  g_h);
    cudaGetSymbolAddress((void**)&xzbuf, g_xz);
    cudaGetSymbolAddress((void**)&ybuf,  g_y);

    dim3 grid_in(2, 128);     // N=256/128,  M=8192/64
    dim3 grid_ip(8, 128);     // N=1024/128
    dim3 grid_op(2, 128);     // N=256/128
    dim3 grid_p1(32, 8, 7);   // chunks 0..6 only
    dim3 grid_p2(32, 8, 8);

    // Launch 0: input projection  h = x @ proj_w^T  [8192,256], K=64
    // (proj_b folded into layer-0 in_proj A-read)
    wgemm_nt_kernel<<<grid_in, 256>>>(x, (const float*)0, proj_w,
                                      hbuf, BT, DMv, Fv);

    for (int l = 0; l < Lv; ++l) {
        const float* abias  = (l == 0) ? proj_b : (const float*)0;
        const float* alog_l = A_log + (size_t)l * DIv * Nv;

        // in_proj: xz = (h+bias?) @ ipw^T   [8192,1024], K=256
        wgemm_nt_kernel<<<grid_ip, 256>>>(hbuf, abias,
                                          ipw + (size_t)l * 262144,
                                          xzbuf, BT, 2*DIv, DMv);

        fused_mid_kernel<<<512, 256>>>(
            cw  + (size_t)l * DIv * DCv,
            cb  + (size_t)l * DIv,
            xpw + (size_t)l * (DTRv + 2*Nv) * DIv,
            dtw + (size_t)l * DIv * DTRv,
            dtb + (size_t)l * DIv);

        // Launch index 3 on l==0 (profiled): scan_pass1
        scan_pass1_kernel<<<grid_p1, 256>>>(alog_l);
        scan_pass2_kernel<<<grid_p2, 256>>>(alog_l, Dp + (size_t)l * DIv);

        // out_proj: h = y @ opw^T   [8192,256], K=512
        wgemm_nt_kernel<<<grid_op, 256>>>(ybuf, (const float*)0,
                                          opw + (size_t)l * 131072,
                                          hbuf, BT, DMv, DIv);
    }

    final_kernel<<<Bv, 256>>>(ln_g, ln_b, head_w, head_b, out);
}

// round 12
// speedup vs baseline: 1.0405x; 1.0405x over previous
#include <cuda_runtime.h>
#include <cuda_bf16.h>
#include <mma.h>
#include <math.h>

using namespace nvcuda;

// ---------------------------------------------------------------------------
// Problem constants
// ---------------------------------------------------------------------------
#define Bv   8
#define Tv   1024
#define Fv   64
#define DMv  256
#define Lv   4
#define DIv  512          // 2*DM
#define Nv   16
#define DCv  4
#define DTRv 16           // DM/16
#define BT   (Bv*Tv)      // 8192
#define NCH  8            // scan chunks
#define CHT  128          // timesteps per chunk

// ---------------------------------------------------------------------------
// Scratch (device globals; no runtime allocation allowed)
// ---------------------------------------------------------------------------
__device__ float g_h  [BT * DMv];
__device__ float g_xz [BT * (2*DIv)];
__device__ float g_xc [BT * DIv];
__device__ float g_dt [BT * DIv];
__device__ float g_BC [BT * (2*Nv)];
__device__ float g_y  [BT * DIv];

__device__ float g_chP[Bv * DIv * Nv * NCH];
__device__ float g_chH[Bv * DIv * Nv * NCH];

// split-bf16 weight buffers: proj_w[16384] | ipw[1048576] | opw[524288]
__device__ __nv_bfloat16 g_whi[1589248];
__device__ __nv_bfloat16 g_wlo[1589248];

// ---------------------------------------------------------------------------
// One-shot weight split (proj_w + ipw + opw).
// float4 regions: proj [0,4096), ipw [4096,266240), opw [266240,397312).
// ---------------------------------------------------------------------------
__global__ void __launch_bounds__(256)
split_all_kernel(const float* __restrict__ proj_w,
                 const float* __restrict__ ipw,
                 const float* __restrict__ opw,
                 __nv_bfloat16* __restrict__ whi,
                 __nv_bfloat16* __restrict__ wlo)
{
    const int i = blockIdx.x * 256 + threadIdx.x;
    const float* src;
    int j, dst;
    if (i < 4096)        { src = proj_w; j = i;           dst = 0; }
    else if (i < 266240) { src = ipw;    j = i - 4096;    dst = 16384; }
    else if (i < 397312) { src = opw;    j = i - 266240;  dst = 1064960; }
    else return;

    const float4 v = *(const float4*)(src + j*4);
    __nv_bfloat16* hi = whi + dst + j*4;
    __nv_bfloat16* lo = wlo + dst + j*4;
    __nv_bfloat16 h0 = __float2bfloat16(v.x);
    __nv_bfloat16 h1 = __float2bfloat16(v.y);
    __nv_bfloat16 h2 = __float2bfloat16(v.z);
    __nv_bfloat16 h3 = __float2bfloat16(v.w);
    __nv_bfloat162 a; a.x = h0; a.y = h1;
    __nv_bfloat162 b; b.x = h2; b.y = h3;
    *(__nv_bfloat162*)(hi)     = a;
    *(__nv_bfloat162*)(hi + 2) = b;
    __nv_bfloat162 c; c.x = __float2bfloat16(v.x - __bfloat162float(h0));
                      c.y = __float2bfloat16(v.y - __bfloat162float(h1));
    __nv_bfloat162 d; d.x = __float2bfloat16(v.z - __bfloat162float(h2));
                      d.y = __float2bfloat16(v.w - __bfloat162float(h3));
    *(__nv_bfloat162*)(lo)     = c;
    *(__nv_bfloat162*)(lo + 2) = d;
}

// ---------------------------------------------------------------------------
// Tensor-core GEMM (R10 version: pre-split W, A split on the fly).
// C[M,N] = (A + Abias_cols)[M,K] @ W[N,K]^T.  BM=64, BN=128, BK=32.
// ---------------------------------------------------------------------------
#define SPAD 40

__global__ void __launch_bounds__(256, 2)
wgemm_nt_kernel(const float* __restrict__ A, const float* __restrict__ Abias,
                const __nv_bfloat16* __restrict__ Whi,
                const __nv_bfloat16* __restrict__ Wlo,
                float* __restrict__ C,
                int M, int N, int K)
{
    __shared__ __align__(16) __nv_bfloat16 Ah[64*SPAD];
    __shared__ __align__(16) __nv_bfloat16 Al[64*SPAD];
    __shared__ __align__(16) __nv_bfloat16 Bh[128*SPAD];
    __shared__ __align__(16) __nv_bfloat16 Bl[128*SPAD];

    const int tid = threadIdx.x;
    const int bm  = blockIdx.y, bn = blockIdx.x;
    const int wid = tid >> 5;
    const int wm  = wid >> 2;
    const int wn  = wid & 3;

    wmma::fragment<wmma::accumulator, 16, 16, 16, float> acc[2][2];
#pragma unroll
    for (int mi = 0; mi < 2; ++mi)
#pragma unroll
        for (int ni = 0; ni < 2; ++ni)
            wmma::fill_fragment(acc[mi][ni], 0.0f);

    for (int k0 = 0; k0 < K; k0 += 32) {
#pragma unroll
        for (int i = 0; i < 2; ++i) {
            const int idx = tid + i * 256;
            const int row = idx >> 3;
            const int kc  = (idx & 7) << 2;
            float4 v = *(const float4*)(A + (size_t)(bm*64 + row) * K + k0 + kc);
            if (Abias) {
                const float4 bb = *(const float4*)(Abias + k0 + kc);
                v.x += bb.x; v.y += bb.y; v.z += bb.z; v.w += bb.w;
            }
            __nv_bfloat16 h0 = __float2bfloat16(v.x);
            __nv_bfloat16 h1 = __float2bfloat16(v.y);
            __nv_bfloat16 h2 = __float2bfloat16(v.z);
            __nv_bfloat16 h3 = __float2bfloat16(v.w);
            __nv_bfloat162 ph0; ph0.x = h0; ph0.y = h1;
            __nv_bfloat162 ph1; ph1.x = h2; ph1.y = h3;
            *(__nv_bfloat162*)(Ah + row*SPAD + kc)     = ph0;
            *(__nv_bfloat162*)(Ah + row*SPAD + kc + 2) = ph1;
            __nv_bfloat162 pl0; pl0.x = __float2bfloat16(v.x - __bfloat162float(h0));
                                pl0.y = __float2bfloat16(v.y - __bfloat162float(h1));
            __nv_bfloat162 pl1; pl1.x = __float2bfloat16(v.z - __bfloat162float(h2));
                                pl1.y = __float2bfloat16(v.w - __bfloat162float(h3));
            *(__nv_bfloat162*)(Al + row*SPAD + kc)     = pl0;
            *(__nv_bfloat162*)(Al + row*SPAD + kc + 2) = pl1;
        }
#pragma unroll
        for (int i = 0; i < 2; ++i) {
            const int idx = tid + i * 256;
            const int row = idx >> 2;
            const int kc  = (idx & 3) << 3;
            const size_t g = (size_t)(bn*128 + row) * K + k0 + kc;
            *(float4*)(Bh + row*SPAD + kc) = *(const float4*)(Whi + g);
            *(float4*)(Bl + row*SPAD + kc) = *(const float4*)(Wlo + g);
        }
        __syncthreads();

#pragma unroll
        for (int ks = 0; ks < 32; ks += 16) {
            wmma::fragment<wmma::matrix_b, 16, 16, 16, __nv_bfloat16, wmma::col_major> bH[2], bL[2];
#pragma unroll
            for (int ni = 0; ni < 2; ++ni) {
                const int rr = wn*32 + ni*16;
                wmma::load_matrix_sync(bH[ni], Bh + rr*SPAD + ks, SPAD);
                wmma::load_matrix_sync(bL[ni], Bl + rr*SPAD + ks, SPAD);
            }
#pragma unroll
            for (int mi = 0; mi < 2; ++mi) {
                wmma::fragment<wmma::matrix_a, 16, 16, 16, __nv_bfloat16, wmma::row_major> aH, aL;
                const int rr = wm*32 + mi*16;
                wmma::load_matrix_sync(aH, Ah + rr*SPAD + ks, SPAD);
                wmma::load_matrix_sync(aL, Al + rr*SPAD + ks, SPAD);
#pragma unroll
                for (int ni = 0; ni < 2; ++ni) {
                    wmma::mma_sync(acc[mi][ni], aH, bH[ni], acc[mi][ni]);
                    wmma::mma_sync(acc[mi][ni], aH, bL[ni], acc[mi][ni]);
                    wmma::mma_sync(acc[mi][ni], aL, bH[ni], acc[mi][ni]);
                }
            }
        }
        __syncthreads();
    }

#pragma unroll
    for (int mi = 0; mi < 2; ++mi)
#pragma unroll
        for (int ni = 0; ni < 2; ++ni) {
            const int rr = bm*64 + wm*32 + mi*16;
            const int cc = bn*128 + wn*32 + ni*16;
            wmma::store_matrix_sync(C + (size_t)rr * N + cc, acc[mi][ni], N,
                                    wmma::mem_row_major);
        }
}

// ---------------------------------------------------------------------------
// Fused middle kernel (R10 version, unchanged).
// ---------------------------------------------------------------------------
__global__ void __launch_bounds__(256)
fused_mid_kernel(const float* __restrict__ conv_w,
                 const float* __restrict__ conv_b,
                 const float* __restrict__ xpw,
                 const float* __restrict__ dtw,
                 const float* __restrict__ dtb)
{
    __shared__ __align__(16) float xc_s  [16][DIv];
    __shared__ __align__(16) float wc_s  [48][68];
    __shared__ __align__(16) float xdbl_s[16][48];

    const int blk = blockIdx.x;
    const int b   = blk >> 6;
    const int t0  = (blk & 63) << 4;
    const int tid = threadIdx.x;

#pragma unroll
    for (int dd = 0; dd < 2; ++dd) {
        const int d = tid + dd * 256;
        const float* xin = g_xz + (size_t)(b * Tv) * (2*DIv) + d;
        const float4 cw4 = *(const float4*)(conv_w + d*4);
        const float  cb  = conv_b[d];
        float x0 = (t0 - 3 >= 0) ? xin[(size_t)(t0-3) * (2*DIv)] : 0.f;
        float x1 = (t0 - 2 >= 0) ? xin[(size_t)(t0-2) * (2*DIv)] : 0.f;
        float x2 = (t0 - 1 >= 0) ? xin[(size_t)(t0-1) * (2*DIv)] : 0.f;
#pragma unroll
        for (int tt = 0; tt < 16; ++tt) {
            const float x3 = xin[(size_t)(t0+tt) * (2*DIv)];
            float s = cw4.x*x0 + cw4.y*x1 + cw4.z*x2 + cw4.w*x3 + cb;
            float sl = s / (1.f + __expf(-s));
            xc_s[tt][d] = sl;
            g_xc[((size_t)(b*Tv + t0 + tt)) * DIv + d] = sl;
            x0 = x1; x1 = x2; x2 = x3;
        }
    }
    __syncthreads();

    const int tt  = tid >> 4;
    const int oth = tid & 15;
    float acc0 = 0.f, acc1 = 0.f, acc2 = 0.f;

    for (int kc = 0; kc < DIv; kc += 64) {
#pragma unroll
        for (int j = 0; j < 3; ++j) {
            const int l4 = tid * 3 + j;
            const int o  = l4 >> 4;
            const int k  = (l4 & 15) << 2;
            *(float4*)&wc_s[o][k] = *(const float4*)(xpw + o*DIv + kc + k);
        }
        __syncthreads();
#pragma unroll
        for (int k = 0; k < 64; k += 4) {
            const float4 xa = *(const float4*)&xc_s[tt][kc + k];
            const float4 w0 = *(const float4*)&wc_s[oth      ][k];
            const float4 w1 = *(const float4*)&wc_s[oth + 16][k];
            const float4 w2 = *(const float4*)&wc_s[oth + 32][k];
            acc0 += xa.x*w0.x + xa.y*w0.y + xa.z*w0.z + xa.w*w0.w;
            acc1 += xa.x*w1.x + xa.y*w1.y + xa.z*w1.z + xa.w*w1.w;
            acc2 += xa.x*w2.x + xa.y*w2.y + xa.z*w2.z + xa.w*w2.w;
        }
        __syncthreads();
    }
    xdbl_s[tt][oth     ] = acc0;
    xdbl_s[tt][oth + 16] = acc1;
    xdbl_s[tt][oth + 32] = acc2;
    __syncthreads();

    {
        int idx = tid;
#pragma unroll
        for (int r = 0; r < 2; ++r, idx += 256) {
            const int tti = idx >> 5, c = idx & 31;
            g_BC[((size_t)(b*Tv + t0 + tti)) * (2*Nv) + c] = xdbl_s[tti][16 + c];
        }
    }

    {
        const int d0 = tid, d1 = tid + 256;
        float w0[16], w1[16];
        *(float4*)&w0[0]  = *(const float4*)(dtw + d0*16 + 0);
        *(float4*)&w0[4]  = *(const float4*)(dtw + d0*16 + 4);
        *(float4*)&w0[8]  = *(const float4*)(dtw + d0*16 + 8);
        *(float4*)&w0[12] = *(const float4*)(dtw + d0*16 + 12);
        *(float4*)&w1[0]  = *(const float4*)(dtw + d1*16 + 0);
        *(float4*)&w1[4]  = *(const float4*)(dtw + d1*16 + 4);
        *(float4*)&w1[8]  = *(const float4*)(dtw + d1*16 + 8);
        *(float4*)&w1[12] = *(const float4*)(dtw + d1*16 + 12);
        const float b0 = dtb[d0], b1 = dtb[d1];

#pragma unroll
        for (int tt2 = 0; tt2 < 16; ++tt2) {
            float xv[16];
            *(float4*)&xv[0]  = *(const float4*)&xdbl_s[tt2][0];
            *(float4*)&xv[4]  = *(const float4*)&xdbl_s[tt2][4];
            *(float4*)&xv[8]  = *(const float4*)&xdbl_s[tt2][8];
            *(float4*)&xv[12] = *(const float4*)&xdbl_s[tt2][12];
            float s0 = b0, s1 = b1;
#pragma unroll
            for (int r = 0; r < 16; ++r) {
                s0 += xv[r] * w0[r];
                s1 += xv[r] * w1[r];
            }
            const float sp0 = fmaxf(s0, 0.f) + log1pf(__expf(-fabsf(s0)));
            const float sp1 = fmaxf(s1, 0.f) + log1pf(__expf(-fabsf(s1)));
            const size_t o = ((size_t)(b*Tv + t0 + tt2)) * DIv;
            g_dt[o + d0] = sp0;
            g_dt[o + d1] = sp1;
        }
    }
}

// ---------------------------------------------------------------------------
// Scan v3: thread-per-channel, h[16]/P[16] in registers, no shuffles.
// Pass 1: per-chunk (P, H) for chunks 0..6.  grid (4, 8, 7), 128 threads.
// ---------------------------------------------------------------------------
__global__ void __launch_bounds__(128)
scan_pass1_kernel(const float* __restrict__ A_log)
{
    __shared__ __align__(16) float s_b[64][16];

    const int tid = threadIdx.x;
    const int d   = blockIdx.x * 128 + tid;
    const int b   = blockIdx.y;
    const int ch  = blockIdx.z;

    float a[16];
    {
        float4 v0 = *(const float4*)(A_log + d*16 + 0);
        float4 v1 = *(const float4*)(A_log + d*16 + 4);
        float4 v2 = *(const float4*)(A_log + d*16 + 8);
        float4 v3 = *(const float4*)(A_log + d*16 + 12);
        a[0]=-__expf(v0.x); a[1]=-__expf(v0.y); a[2]=-__expf(v0.z); a[3]=-__expf(v0.w);
        a[4]=-__expf(v1.x); a[5]=-__expf(v1.y); a[6]=-__expf(v1.z); a[7]=-__expf(v1.w);
        a[8]=-__expf(v2.x); a[9]=-__expf(v2.y); a[10]=-__expf(v2.z); a[11]=-__expf(v2.w);
        a[12]=-__expf(v3.x); a[13]=-__expf(v3.y); a[14]=-__expf(v3.z); a[15]=-__expf(v3.w);
    }

    float h[16], P[16];
#pragma unroll
    for (int n = 0; n < 16; ++n) { h[n] = 0.f; P[n] = 1.f; }

    for (int sc = 0; sc < 2; ++sc) {
        const int base = b * Tv + ch * CHT + sc * 64;
        // stage B[64][16]
#pragma unroll
        for (int i = 0; i < 8; ++i) {
            const int idx = tid + i * 128;
            const int t = idx >> 4, n = idx & 15;
            s_b[t][n] = g_BC[(size_t)(base + t) * (2*Nv) + n];
        }
        __syncthreads();

#pragma unroll 2
        for (int t = 0; t < 64; ++t) {
            const float dtv = g_dt[(size_t)(base + t) * DIv + d];
            const float uv  = g_xc[(size_t)(base + t) * DIv + d];
            const float dtu = dtv * uv;
            const float4 B0 = *(const float4*)&s_b[t][0];
            const float4 B1 = *(const float4*)&s_b[t][4];
            const float4 B2 = *(const float4*)&s_b[t][8];
            const float4 B3 = *(const float4*)&s_b[t][12];
            const float Bs[16] = {B0.x,B0.y,B0.z,B0.w, B1.x,B1.y,B1.z,B1.w,
                                  B2.x,B2.y,B2.z,B2.w, B3.x,B3.y,B3.z,B3.w};
#pragma unroll
            for (int n = 0; n < 16; ++n) {
                const float e = __expf(dtv * a[n]);
                h[n] = e * h[n] + dtu * Bs[n];
                P[n] *= e;
            }
        }
        __syncthreads();
    }

    const size_t o = (((size_t)b * DIv + d) * Nv) * NCH + ch;
#pragma unroll
    for (int n = 0; n < 16; ++n) {
        g_chP[o + n*NCH] = P[n];
        g_chH[o + n*NCH] = h[n];
    }
}

// ---------------------------------------------------------------------------
// Scan v3 pass 2: seed folded inline, full scan, gated y (coalesced stores).
// grid (4, 8, 8), 128 threads.
// ---------------------------------------------------------------------------
__global__ void __launch_bounds__(128)
scan_pass2_kernel(const float* __restrict__ A_log, const float* __restrict__ Dp)
{
    __shared__ __align__(16) float s_bc[64][32];

    const int tid = threadIdx.x;
    const int d   = blockIdx.x * 128 + tid;
    const int b   = blockIdx.y;
    const int ch  = blockIdx.z;

    float a[16];
    {
        float4 v0 = *(const float4*)(A_log + d*16 + 0);
        float4 v1 = *(const float4*)(A_log + d*16 + 4);
        float4 v2 = *(const float4*)(A_log + d*16 + 8);
        float4 v3 = *(const float4*)(A_log + d*16 + 12);
        a[0]=-__expf(v0.x); a[1]=-__expf(v0.y); a[2]=-__expf(v0.z); a[3]=-__expf(v0.w);
        a[4]=-__expf(v1.x); a[5]=-__expf(v1.y); a[6]=-__expf(v1.z); a[7]=-__expf(v1.w);
        a[8]=-__expf(v2.x); a[9]=-__expf(v2.y); a[10]=-__expf(v2.z); a[11]=-__expf(v2.w);
        a[12]=-__expf(v3.x); a[13]=-__expf(v3.y); a[14]=-__expf(v3.z); a[15]=-__expf(v3.w);
    }
    const float dcoef = Dp[d];

    // seed: fold (P,H) over chunks 0..ch-1 for each n
    float h[16];
    {
        const size_t sb = (((size_t)b * DIv + d) * Nv) * NCH;
#pragma unroll
        for (int n = 0; n < 16; ++n) {
            float hh = 0.f;
            for (int c = 0; c < ch; ++c)
                hh = g_chP[sb + n*NCH + c] * hh + g_chH[sb + n*NCH + c];
            h[n] = hh;
        }
    }

    for (int sc = 0; sc < 2; ++sc) {
        const int base = b * Tv + ch * CHT + sc * 64;
        // stage B|C [64][32]
#pragma unroll
        for (int i = 0; i < 16; ++i) {
            const int idx = tid + i * 128;
            const int t = idx >> 5, c = idx & 31;
            s_bc[t][c] = g_BC[(size_t)(base + t) * (2*Nv) + c];
        }
        __syncthreads();

#pragma unroll 2
        for (int t = 0; t < 64; ++t) {
            const float dtv = g_dt[(size_t)(base + t) * DIv + d];
            const float uv  = g_xc[(size_t)(base + t) * DIv + d];
            const float zv  = g_xz[(size_t)(base + t) * (2*DIv) + DIv + d];
            const float dtu = dtv * uv;
            const float4 B0 = *(const float4*)&s_bc[t][0];
            const float4 B1 = *(const float4*)&s_bc[t][4];
            const float4 B2 = *(const float4*)&s_bc[t][8];
            const float4 B3 = *(const float4*)&s_bc[t][12];
            const float4 C0 = *(const float4*)&s_bc[t][16];
            const float4 C1 = *(const float4*)&s_bc[t][20];
            const float4 C2 = *(const float4*)&s_bc[t][24];
            const float4 C3 = *(const float4*)&s_bc[t][28];
            const float Bs[16] = {B0.x,B0.y,B0.z,B0.w, B1.x,B1.y,B1.z,B1.w,
                                  B2.x,B2.y,B2.z,B2.w, B3.x,B3.y,B3.z,B3.w};
            const float Cs[16] = {C0.x,C0.y,C0.z,C0.w, C1.x,C1.y,C1.z,C1.w,
                                  C2.x,C2.y,C2.z,C2.w, C3.x,C3.y,C3.z,C3.w};
            float y = 0.f;
#pragma unroll
            for (int n = 0; n < 16; ++n) {
                const float e = __expf(dtv * a[n]);
                h[n] = e * h[n] + dtu * Bs[n];
                y += h[n] * Cs[n];
            }
            y += dcoef * uv;
            y *= zv / (1.f + __expf(-zv));
            g_y[(size_t)(base + t) * DIv + d] = y;
        }
        __syncthreads();
    }
}

// ---------------------------------------------------------------------------
// Final: LayerNorm(last token) + head.
// ---------------------------------------------------------------------------
__global__ void __launch_bounds__(256)
final_kernel(const float* __restrict__ ln_g, const float* __restrict__ ln_b,
             const float* __restrict__ head_w, const float* __restrict__ head_b,
             float* __restrict__ out)
{
    __shared__ float red[256];
    const int b = blockIdx.x, tid = threadIdx.x;
    const float v = g_h[((size_t)(b * Tv + (Tv - 1))) * DMv + tid];

    red[tid] = v; __syncthreads();
    for (int s = 128; s > 0; s >>= 1) { if (tid < s) red[tid] += red[tid + s]; __syncthreads(); }
    const float mu = red[0] * (1.f / DMv);
    __syncthreads();

    const float dv = v - mu;
    red[tid] = dv * dv; __syncthreads();
    for (int s = 128; s > 0; s >>= 1) { if (tid < s) red[tid] += red[tid + s]; __syncthreads(); }
    const float var = red[0] * (1.f / DMv);
    __syncthreads();

    const float hn = dv * rsqrtf(var + 1e-5f) * ln_g[tid] + ln_b[tid];
    red[tid] = hn * head_w[tid]; __syncthreads();
    for (int s = 128; s > 0; s >>= 1) { if (tid < s) red[tid] += red[tid + s]; __syncthreads(); }
    if (tid == 0) out[b] = red[0] + head_b[0];
}

// ---------------------------------------------------------------------------
// Host launcher
// ---------------------------------------------------------------------------
extern "C" void kernel_launch(void* const* d_in, const int* in_sizes, int n_in,
                              void* d_out, int out_size)
{
    const float* x      = (const float*)d_in[0];
    const float* proj_w = (const float*)d_in[1];
    const float* proj_b = (const float*)d_in[2];
    const float* ipw    = (const float*)d_in[3];
    const float* cw     = (const float*)d_in[4];
    const float* cb     = (const float*)d_in[5];
    const float* xpw    = (const float*)d_in[6];
    const float* dtw    = (const float*)d_in[7];
    const float* dtb    = (const float*)d_in[8];
    const float* A_log  = (const float*)d_in[9];
    const float* Dp     = (const float*)d_in[10];
    const float* opw    = (const float*)d_in[11];
    const float* ln_g   = (const float*)d_in[12];
    const float* ln_b   = (const float*)d_in[13];
    const float* head_w = (const float*)d_in[14];
    const float* head_b = (const float*)d_in[15];
    float* out = (float*)d_out;

    float *hbuf, *xzbuf, *ybuf;
    __nv_bfloat16 *whi, *wlo;
    cudaGetSymbolAddress((void**)&hbuf,  g_h);
    cudaGetSymbolAddress((void**)&xzbuf, g_xz);
    cudaGetSymbolAddress((void**)&ybuf,  g_y);
    cudaGetSymbolAddress((void**)&whi,   g_whi);
    cudaGetSymbolAddress((void**)&wlo,   g_wlo);

    __nv_bfloat16* whi_proj = whi;
    __nv_bfloat16* wlo_proj = wlo;
    __nv_bfloat16* whi_ipw  = whi + 16384;
    __nv_bfloat16* wlo_ipw  = wlo + 16384;
    __nv_bfloat16* whi_opw  = whi + 1064960;
    __nv_bfloat16* wlo_opw  = wlo + 1064960;

    // Launch 1: all weight splits.
    split_all_kernel<<<1552, 256>>>(proj_w, ipw, opw, whi, wlo);

    dim3 grid_in(2, 128);
    dim3 grid_ip(8, 128);
    dim3 grid_op(2, 128);
    dim3 grid_p1(4, 8, 7);    // chunks 0..6
    dim3 grid_p2(4, 8, 8);

    // Launch 2: input projection  h = x @ proj_w^T  [8192,256], K=64
    wgemm_nt_kernel<<<grid_in, 256>>>(x, (const float*)0,
                                      whi_proj, wlo_proj, hbuf, BT, DMv, Fv);

    for (int l = 0; l < Lv; ++l) {
        const size_t ipoff = (size_t)l * 262144;
        const size_t opoff = (size_t)l * 131072;
        const float* abias  = (l == 0) ? proj_b : (const float*)0;
        const float* alog_l = A_log + (size_t)l * DIv * Nv;

        // in_proj: xz = (h+bias?) @ ipw^T   [8192,1024], K=256
        wgemm_nt_kernel<<<grid_ip, 256>>>(hbuf, abias,
                                          whi_ipw + ipoff, wlo_ipw + ipoff,
                                          xzbuf, BT, 2*DIv, DMv);

        fused_mid_kernel<<<512, 256>>>(
            cw  + (size_t)l * DIv * DCv,
            cb  + (size_t)l * DIv,
            xpw + (size_t)l * (DTRv + 2*Nv) * DIv,
            dtw + (size_t)l * DIv * DTRv,
            dtb + (size_t)l * DIv);

        scan_pass1_kernel<<<grid_p1, 128>>>(alog_l);
        scan_pass2_kernel<<<grid_p2, 128>>>(alog_l, Dp + (size_t)l * DIv);

        // out_proj: h = y @ opw^T   [8192,256], K=512
        wgemm_nt_kernel<<<grid_op, 256>>>(ybuf, (const float*)0,
                                          whi_opw + opoff, wlo_opw + opoff,
                                          hbuf, BT, DMv, DIv);
    }

    final_kernel<<<Bv, 256>>>(ln_g, ln_b, head_w, head_b, out);
}

// round 13
// speedup vs baseline: 1.1012x; 1.0583x over previous
#include <cuda_runtime.h>
#include <cuda_bf16.h>
#include <mma.h>
#include <math.h>

using namespace nvcuda;

// ---------------------------------------------------------------------------
// Problem constants
// ---------------------------------------------------------------------------
#define Bv   8
#define Tv   1024
#define Fv   64
#define DMv  256
#define Lv   4
#define DIv  512          // 2*DM
#define Nv   16
#define DCv  4
#define DTRv 16           // DM/16
#define BT   (Bv*Tv)      // 8192
#define NCH  8            // scan chunks
#define CHT  128          // timesteps per chunk

// ---------------------------------------------------------------------------
// Scratch (device globals; no runtime allocation allowed)
// ---------------------------------------------------------------------------
__device__ float g_h   [BT * DMv];
__device__ float g_xz  [BT * (2*DIv)];
__device__ float g_xc  [BT * DIv];
__device__ float g_dt  [BT * DIv];
__device__ float g_BC  [BT * (2*Nv)];
__device__ float g_y   [BT * DIv];
__device__ float g_xdbl[BT * 64];          // padded x_proj output (48 real)

__device__ float g_chP[Bv * DIv * Nv * NCH];
__device__ float g_chH[Bv * DIv * Nv * NCH];

// split-bf16 weights: proj[16384] | ipw[1048576] | opw[524288] | xpw_pad[131072]
#define W_PROJ 0
#define W_IPW  16384
#define W_OPW  1064960
#define W_XPW  1589248
__device__ __nv_bfloat16 g_whi[1720320];
__device__ __nv_bfloat16 g_wlo[1720320];

// ---------------------------------------------------------------------------
// One-shot weight split.  float4 regions:
//   proj [0,4096) | ipw [4096,266240) | opw [266240,397312) |
//   xpw padded to [4][64][512] at [397312,430080)
// grid = 1680 x 256.
// ---------------------------------------------------------------------------
__global__ void __launch_bounds__(256)
split_all_kernel(const float* __restrict__ proj_w,
                 const float* __restrict__ ipw,
                 const float* __restrict__ opw,
                 const float* __restrict__ xpw,
                 __nv_bfloat16* __restrict__ whi,
                 __nv_bfloat16* __restrict__ wlo)
{
    const int i = blockIdx.x * 256 + threadIdx.x;
    float4 v;
    int dst_el;
    if (i < 4096) {
        v = *(const float4*)(proj_w + i*4);
        dst_el = W_PROJ + i*4;
    } else if (i < 266240) {
        const int j = i - 4096;
        v = *(const float4*)(ipw + (size_t)j*4);
        dst_el = W_IPW + j*4;
    } else if (i < 397312) {
        const int j = i - 266240;
        v = *(const float4*)(opw + (size_t)j*4);
        dst_el = W_OPW + j*4;
    } else if (i < 430080) {
        const int j  = i - 397312;          // padded float4 index
        const int el = j * 4;               // element in [4][64][512]
        const int l  = el >> 15;            // 32768 elems per layer
        const int rm = el & 32767;
        const int o  = rm >> 9;             // padded row 0..63
        const int k  = rm & 511;
        if (o < 48) v = *(const float4*)(xpw + (size_t)l*48*512 + o*512 + k);
        else        { v.x = 0.f; v.y = 0.f; v.z = 0.f; v.w = 0.f; }
        dst_el = W_XPW + el;
    } else return;

    __nv_bfloat16* hi = whi + dst_el;
    __nv_bfloat16* lo = wlo + dst_el;
    __nv_bfloat16 h0 = __float2bfloat16(v.x);
    __nv_bfloat16 h1 = __float2bfloat16(v.y);
    __nv_bfloat16 h2 = __float2bfloat16(v.z);
    __nv_bfloat16 h3 = __float2bfloat16(v.w);
    hi[0] = h0; hi[1] = h1; hi[2] = h2; hi[3] = h3;
    lo[0] = __float2bfloat16(v.x - __bfloat162float(h0));
    lo[1] = __float2bfloat16(v.y - __bfloat162float(h1));
    lo[2] = __float2bfloat16(v.z - __bfloat162float(h2));
    lo[3] = __float2bfloat16(v.w - __bfloat162float(h3));
}

// ---------------------------------------------------------------------------
// Tensor-core GEMM (BN=128, R10/R12 version, unchanged).
// ---------------------------------------------------------------------------
#define SPAD 40

__global__ void __launch_bounds__(256, 2)
wgemm_nt_kernel(const float* __restrict__ A, const float* __restrict__ Abias,
                const __nv_bfloat16* __restrict__ Whi,
                const __nv_bfloat16* __restrict__ Wlo,
                float* __restrict__ C,
                int M, int N, int K)
{
    __shared__ __align__(16) __nv_bfloat16 Ah[64*SPAD];
    __shared__ __align__(16) __nv_bfloat16 Al[64*SPAD];
    __shared__ __align__(16) __nv_bfloat16 Bh[128*SPAD];
    __shared__ __align__(16) __nv_bfloat16 Bl[128*SPAD];

    const int tid = threadIdx.x;
    const int bm  = blockIdx.y, bn = blockIdx.x;
    const int wid = tid >> 5;
    const int wm  = wid >> 2;
    const int wn  = wid & 3;

    wmma::fragment<wmma::accumulator, 16, 16, 16, float> acc[2][2];
#pragma unroll
    for (int mi = 0; mi < 2; ++mi)
#pragma unroll
        for (int ni = 0; ni < 2; ++ni)
            wmma::fill_fragment(acc[mi][ni], 0.0f);

    for (int k0 = 0; k0 < K; k0 += 32) {
#pragma unroll
        for (int i = 0; i < 2; ++i) {
            const int idx = tid + i * 256;
            const int row = idx >> 3;
            const int kc  = (idx & 7) << 2;
            float4 v = *(const float4*)(A + (size_t)(bm*64 + row) * K + k0 + kc);
            if (Abias) {
                const float4 bb = *(const float4*)(Abias + k0 + kc);
                v.x += bb.x; v.y += bb.y; v.z += bb.z; v.w += bb.w;
            }
            __nv_bfloat16 h0 = __float2bfloat16(v.x);
            __nv_bfloat16 h1 = __float2bfloat16(v.y);
            __nv_bfloat16 h2 = __float2bfloat16(v.z);
            __nv_bfloat16 h3 = __float2bfloat16(v.w);
            __nv_bfloat162 ph0; ph0.x = h0; ph0.y = h1;
            __nv_bfloat162 ph1; ph1.x = h2; ph1.y = h3;
            *(__nv_bfloat162*)(Ah + row*SPAD + kc)     = ph0;
            *(__nv_bfloat162*)(Ah + row*SPAD + kc + 2) = ph1;
            __nv_bfloat162 pl0; pl0.x = __float2bfloat16(v.x - __bfloat162float(h0));
                                pl0.y = __float2bfloat16(v.y - __bfloat162float(h1));
            __nv_bfloat162 pl1; pl1.x = __float2bfloat16(v.z - __bfloat162float(h2));
                                pl1.y = __float2bfloat16(v.w - __bfloat162float(h3));
            *(__nv_bfloat162*)(Al + row*SPAD + kc)     = pl0;
            *(__nv_bfloat162*)(Al + row*SPAD + kc + 2) = pl1;
        }
#pragma unroll
        for (int i = 0; i < 2; ++i) {
            const int idx = tid + i * 256;
            const int row = idx >> 2;
            const int kc  = (idx & 3) << 3;
            const size_t g = (size_t)(bn*128 + row) * K + k0 + kc;
            *(float4*)(Bh + row*SPAD + kc) = *(const float4*)(Whi + g);
            *(float4*)(Bl + row*SPAD + kc) = *(const float4*)(Wlo + g);
        }
        __syncthreads();

#pragma unroll
        for (int ks = 0; ks < 32; ks += 16) {
            wmma::fragment<wmma::matrix_b, 16, 16, 16, __nv_bfloat16, wmma::col_major> bH[2], bL[2];
#pragma unroll
            for (int ni = 0; ni < 2; ++ni) {
                const int rr = wn*32 + ni*16;
                wmma::load_matrix_sync(bH[ni], Bh + rr*SPAD + ks, SPAD);
                wmma::load_matrix_sync(bL[ni], Bl + rr*SPAD + ks, SPAD);
            }
#pragma unroll
            for (int mi = 0; mi < 2; ++mi) {
                wmma::fragment<wmma::matrix_a, 16, 16, 16, __nv_bfloat16, wmma::row_major> aH, aL;
                const int rr = wm*32 + mi*16;
                wmma::load_matrix_sync(aH, Ah + rr*SPAD + ks, SPAD);
                wmma::load_matrix_sync(aL, Al + rr*SPAD + ks, SPAD);
#pragma unroll
                for (int ni = 0; ni < 2; ++ni) {
                    wmma::mma_sync(acc[mi][ni], aH, bH[ni], acc[mi][ni]);
                    wmma::mma_sync(acc[mi][ni], aH, bL[ni], acc[mi][ni]);
                    wmma::mma_sync(acc[mi][ni], aL, bH[ni], acc[mi][ni]);
                }
            }
        }
        __syncthreads();
    }

#pragma unroll
    for (int mi = 0; mi < 2; ++mi)
#pragma unroll
        for (int ni = 0; ni < 2; ++ni) {
            const int rr = bm*64 + wm*32 + mi*16;
            const int cc = bn*128 + wn*32 + ni*16;
            wmma::store_matrix_sync(C + (size_t)rr * N + cc, acc[mi][ni], N,
                                    wmma::mem_row_major);
        }
}

// ---------------------------------------------------------------------------
// BN=64 GEMM variant for x_proj: C[8192,64] = A[8192,512] @ W[64,512]^T.
// 8 warps as 4(m) x 2(n); warp tile 16x32.  grid (1, M/64).
// ---------------------------------------------------------------------------
__global__ void __launch_bounds__(256, 2)
wgemm64_kernel(const float* __restrict__ A,
               const __nv_bfloat16* __restrict__ Whi,
               const __nv_bfloat16* __restrict__ Wlo,
               float* __restrict__ C, int K)
{
    __shared__ __align__(16) __nv_bfloat16 Ah[64*SPAD];
    __shared__ __align__(16) __nv_bfloat16 Al[64*SPAD];
    __shared__ __align__(16) __nv_bfloat16 Bh[64*SPAD];
    __shared__ __align__(16) __nv_bfloat16 Bl[64*SPAD];

    const int tid = threadIdx.x;
    const int bm  = blockIdx.y;
    const int wid = tid >> 5;
    const int wm  = wid >> 1;        // 0..3 -> 16 rows each
    const int wn  = wid & 1;         // 0..1 -> 32 cols each

    wmma::fragment<wmma::accumulator, 16, 16, 16, float> acc[2];
    wmma::fill_fragment(acc[0], 0.0f);
    wmma::fill_fragment(acc[1], 0.0f);

    for (int k0 = 0; k0 < K; k0 += 32) {
        // stage A (fp32 -> hi/lo)
#pragma unroll
        for (int i = 0; i < 2; ++i) {
            const int idx = tid + i * 256;
            const int row = idx >> 3;
            const int kc  = (idx & 7) << 2;
            const float4 v = *(const float4*)(A + (size_t)(bm*64 + row) * K + k0 + kc);
            __nv_bfloat16 h0 = __float2bfloat16(v.x);
            __nv_bfloat16 h1 = __float2bfloat16(v.y);
            __nv_bfloat16 h2 = __float2bfloat16(v.z);
            __nv_bfloat16 h3 = __float2bfloat16(v.w);
            __nv_bfloat162 ph0; ph0.x = h0; ph0.y = h1;
            __nv_bfloat162 ph1; ph1.x = h2; ph1.y = h3;
            *(__nv_bfloat162*)(Ah + row*SPAD + kc)     = ph0;
            *(__nv_bfloat162*)(Ah + row*SPAD + kc + 2) = ph1;
            __nv_bfloat162 pl0; pl0.x = __float2bfloat16(v.x - __bfloat162float(h0));
                                pl0.y = __float2bfloat16(v.y - __bfloat162float(h1));
            __nv_bfloat162 pl1; pl1.x = __float2bfloat16(v.z - __bfloat162float(h2));
                                pl1.y = __float2bfloat16(v.w - __bfloat162float(h3));
            *(__nv_bfloat162*)(Al + row*SPAD + kc)     = pl0;
            *(__nv_bfloat162*)(Al + row*SPAD + kc + 2) = pl1;
        }
        // stage W (pre-split bf16), 64 rows x 32 halves = 256 float4s per buf
        {
            const int row = tid >> 2;
            const int kc  = (tid & 3) << 3;
            const size_t g = (size_t)row * K + k0 + kc;
            *(float4*)(Bh + row*SPAD + kc) = *(const float4*)(Whi + g);
            *(float4*)(Bl + row*SPAD + kc) = *(const float4*)(Wlo + g);
        }
        __syncthreads();

#pragma unroll
        for (int ks = 0; ks < 32; ks += 16) {
            wmma::fragment<wmma::matrix_b, 16, 16, 16, __nv_bfloat16, wmma::col_major> bH[2], bL[2];
#pragma unroll
            for (int ni = 0; ni < 2; ++ni) {
                const int rr = wn*32 + ni*16;
                wmma::load_matrix_sync(bH[ni], Bh + rr*SPAD + ks, SPAD);
                wmma::load_matrix_sync(bL[ni], Bl + rr*SPAD + ks, SPAD);
            }
            wmma::fragment<wmma::matrix_a, 16, 16, 16, __nv_bfloat16, wmma::row_major> aH, aL;
            wmma::load_matrix_sync(aH, Ah + (wm*16)*SPAD + ks, SPAD);
            wmma::load_matrix_sync(aL, Al + (wm*16)*SPAD + ks, SPAD);
#pragma unroll
            for (int ni = 0; ni < 2; ++ni) {
                wmma::mma_sync(acc[ni], aH, bH[ni], acc[ni]);
                wmma::mma_sync(acc[ni], aH, bL[ni], acc[ni]);
                wmma::mma_sync(acc[ni], aL, bH[ni], acc[ni]);
            }
        }
        __syncthreads();
    }

#pragma unroll
    for (int ni = 0; ni < 2; ++ni) {
        const int rr = bm*64 + wm*16;
        const int cc = wn*32 + ni*16;
        wmma::store_matrix_sync(C + (size_t)rr * 64 + cc, acc[ni], 64,
                                wmma::mem_row_major);
    }
}

// ---------------------------------------------------------------------------
// conv(4) + bias + SiLU -> g_xc.  512 blocks, 256 threads; 2 channels/thread,
// 16 timesteps.
// ---------------------------------------------------------------------------
__global__ void __launch_bounds__(256)
conv_silu_kernel(const float* __restrict__ conv_w,
                 const float* __restrict__ conv_b)
{
    const int blk = blockIdx.x;
    const int b   = blk >> 6;
    const int t0  = (blk & 63) << 4;
    const int tid = threadIdx.x;

#pragma unroll
    for (int dd = 0; dd < 2; ++dd) {
        const int d = tid + dd * 256;
        const float* xin = g_xz + (size_t)(b * Tv) * (2*DIv) + d;
        const float4 cw4 = *(const float4*)(conv_w + d*4);
        const float  cb  = conv_b[d];
        float x0 = (t0 - 3 >= 0) ? xin[(size_t)(t0-3) * (2*DIv)] : 0.f;
        float x1 = (t0 - 2 >= 0) ? xin[(size_t)(t0-2) * (2*DIv)] : 0.f;
        float x2 = (t0 - 1 >= 0) ? xin[(size_t)(t0-1) * (2*DIv)] : 0.f;
#pragma unroll
        for (int tt = 0; tt < 16; ++tt) {
            const float x3 = xin[(size_t)(t0+tt) * (2*DIv)];
            float s = cw4.x*x0 + cw4.y*x1 + cw4.z*x2 + cw4.w*x3 + cb;
            g_xc[((size_t)(b*Tv + t0 + tt)) * DIv + d] = s / (1.f + __expf(-s));
            x0 = x1; x1 = x2; x2 = x3;
        }
    }
}

// ---------------------------------------------------------------------------
// dt_proj + softplus + B/C extraction from g_xdbl.
// 512 blocks (b, 16-t chunk), 256 threads.
// ---------------------------------------------------------------------------
__global__ void __launch_bounds__(256)
dtproj_bc_kernel(const float* __restrict__ dtw, const float* __restrict__ dtb)
{
    const int blk = blockIdx.x;
    const int b   = blk >> 6;
    const int t0  = (blk & 63) << 4;
    const int tid = threadIdx.x;
    const int row0 = b * Tv + t0;

    // B/C copy: 16 rows x 32 cols
    {
        int idx = tid;
#pragma unroll
        for (int r = 0; r < 2; ++r, idx += 256) {
            const int tti = idx >> 5, c = idx & 31;
            g_BC[((size_t)(row0 + tti)) * (2*Nv) + c] =
                g_xdbl[((size_t)(row0 + tti)) * 64 + 16 + c];
        }
    }

    // dt_proj: 2 channels per thread, weights in regs
    const int d0 = tid, d1 = tid + 256;
    float w0[16], w1[16];
    *(float4*)&w0[0]  = *(const float4*)(dtw + d0*16 + 0);
    *(float4*)&w0[4]  = *(const float4*)(dtw + d0*16 + 4);
    *(float4*)&w0[8]  = *(const float4*)(dtw + d0*16 + 8);
    *(float4*)&w0[12] = *(const float4*)(dtw + d0*16 + 12);
    *(float4*)&w1[0]  = *(const float4*)(dtw + d1*16 + 0);
    *(float4*)&w1[4]  = *(const float4*)(dtw + d1*16 + 4);
    *(float4*)&w1[8]  = *(const float4*)(dtw + d1*16 + 8);
    *(float4*)&w1[12] = *(const float4*)(dtw + d1*16 + 12);
    const float b0 = dtb[d0], b1 = dtb[d1];

#pragma unroll
    for (int tt = 0; tt < 16; ++tt) {
        const float* xr = g_xdbl + (size_t)(row0 + tt) * 64;
        float xv[16];
        *(float4*)&xv[0]  = *(const float4*)(xr + 0);
        *(float4*)&xv[4]  = *(const float4*)(xr + 4);
        *(float4*)&xv[8]  = *(const float4*)(xr + 8);
        *(float4*)&xv[12] = *(const float4*)(xr + 12);
        float s0 = b0, s1 = b1;
#pragma unroll
        for (int r = 0; r < 16; ++r) {
            s0 += xv[r] * w0[r];
            s1 += xv[r] * w1[r];
        }
        const float sp0 = fmaxf(s0, 0.f) + log1pf(__expf(-fabsf(s0)));
        const float sp1 = fmaxf(s1, 0.f) + log1pf(__expf(-fabsf(s1)));
        const size_t o = ((size_t)(row0 + tt)) * DIv;
        g_dt[o + d0] = sp0;
        g_dt[o + d1] = sp1;
    }
}

// ---------------------------------------------------------------------------
// Scan v3 pass 1 (unchanged from R12).  grid (4, 8, 7), 128 threads.
// ---------------------------------------------------------------------------
__global__ void __launch_bounds__(128)
scan_pass1_kernel(const float* __restrict__ A_log)
{
    __shared__ __align__(16) float s_b[64][16];

    const int tid = threadIdx.x;
    const int d   = blockIdx.x * 128 + tid;
    const int b   = blockIdx.y;
    const int ch  = blockIdx.z;

    float a[16];
    {
        float4 v0 = *(const float4*)(A_log + d*16 + 0);
        float4 v1 = *(const float4*)(A_log + d*16 + 4);
        float4 v2 = *(const float4*)(A_log + d*16 + 8);
        float4 v3 = *(const float4*)(A_log + d*16 + 12);
        a[0]=-__expf(v0.x); a[1]=-__expf(v0.y); a[2]=-__expf(v0.z); a[3]=-__expf(v0.w);
        a[4]=-__expf(v1.x); a[5]=-__expf(v1.y); a[6]=-__expf(v1.z); a[7]=-__expf(v1.w);
        a[8]=-__expf(v2.x); a[9]=-__expf(v2.y); a[10]=-__expf(v2.z); a[11]=-__expf(v2.w);
        a[12]=-__expf(v3.x); a[13]=-__expf(v3.y); a[14]=-__expf(v3.z); a[15]=-__expf(v3.w);
    }

    float h[16], P[16];
#pragma unroll
    for (int n = 0; n < 16; ++n) { h[n] = 0.f; P[n] = 1.f; }

    for (int sc = 0; sc < 2; ++sc) {
        const int base = b * Tv + ch * CHT + sc * 64;
#pragma unroll
        for (int i = 0; i < 8; ++i) {
            const int idx = tid + i * 128;
            const int t = idx >> 4, n = idx & 15;
            s_b[t][n] = g_BC[(size_t)(base + t) * (2*Nv) + n];
        }
        __syncthreads();

#pragma unroll 2
        for (int t = 0; t < 64; ++t) {
            const float dtv = g_dt[(size_t)(base + t) * DIv + d];
            const float uv  = g_xc[(size_t)(base + t) * DIv + d];
            const float dtu = dtv * uv;
            const float4 B0 = *(const float4*)&s_b[t][0];
            const float4 B1 = *(const float4*)&s_b[t][4];
            const float4 B2 = *(const float4*)&s_b[t][8];
            const float4 B3 = *(const float4*)&s_b[t][12];
            const float Bs[16] = {B0.x,B0.y,B0.z,B0.w, B1.x,B1.y,B1.z,B1.w,
                                  B2.x,B2.y,B2.z,B2.w, B3.x,B3.y,B3.z,B3.w};
#pragma unroll
            for (int n = 0; n < 16; ++n) {
                const float e = __expf(dtv * a[n]);
                h[n] = e * h[n] + dtu * Bs[n];
                P[n] *= e;
            }
        }
        __syncthreads();
    }

    const size_t o = (((size_t)b * DIv + d) * Nv) * NCH + ch;
#pragma unroll
    for (int n = 0; n < 16; ++n) {
        g_chP[o + n*NCH] = P[n];
        g_chH[o + n*NCH] = h[n];
    }
}

// ---------------------------------------------------------------------------
// Scan v3 pass 2 (unchanged from R12).  grid (4, 8, 8), 128 threads.
// ---------------------------------------------------------------------------
__global__ void __launch_bounds__(128)
scan_pass2_kernel(const float* __restrict__ A_log, const float* __restrict__ Dp)
{
    __shared__ __align__(16) float s_bc[64][32];

    const int tid = threadIdx.x;
    const int d   = blockIdx.x * 128 + tid;
    const int b   = blockIdx.y;
    const int ch  = blockIdx.z;

    float a[16];
    {
        float4 v0 = *(const float4*)(A_log + d*16 + 0);
        float4 v1 = *(const float4*)(A_log + d*16 + 4);
        float4 v2 = *(const float4*)(A_log + d*16 + 8);
        float4 v3 = *(const float4*)(A_log + d*16 + 12);
        a[0]=-__expf(v0.x); a[1]=-__expf(v0.y); a[2]=-__expf(v0.z); a[3]=-__expf(v0.w);
        a[4]=-__expf(v1.x); a[5]=-__expf(v1.y); a[6]=-__expf(v1.z); a[7]=-__expf(v1.w);
        a[8]=-__expf(v2.x); a[9]=-__expf(v2.y); a[10]=-__expf(v2.z); a[11]=-__expf(v2.w);
        a[12]=-__expf(v3.x); a[13]=-__expf(v3.y); a[14]=-__expf(v3.z); a[15]=-__expf(v3.w);
    }
    const float dcoef = Dp[d];

    float h[16];
    {
        const size_t sb = (((size_t)b * DIv + d) * Nv) * NCH;
#pragma unroll
        for (int n = 0; n < 16; ++n) {
            float hh = 0.f;
            for (int c = 0; c < ch; ++c)
                hh = g_chP[sb + n*NCH + c] * hh + g_chH[sb + n*NCH + c];
            h[n] = hh;
        }
    }

    for (int sc = 0; sc < 2; ++sc) {
        const int base = b * Tv + ch * CHT + sc * 64;
#pragma unroll
        for (int i = 0; i < 16; ++i) {
            const int idx = tid + i * 128;
            const int t = idx >> 5, c = idx & 31;
            s_bc[t][c] = g_BC[(size_t)(base + t) * (2*Nv) + c];
        }
        __syncthreads();

#pragma unroll 2
        for (int t = 0; t < 64; ++t) {
            const float dtv = g_dt[(size_t)(base + t) * DIv + d];
            const float uv  = g_xc[(size_t)(base + t) * DIv + d];
            const float zv  = g_xz[(size_t)(base + t) * (2*DIv) + DIv + d];
            const float dtu = dtv * uv;
            const float4 B0 = *(const float4*)&s_bc[t][0];
            const float4 B1 = *(const float4*)&s_bc[t][4];
            const float4 B2 = *(const float4*)&s_bc[t][8];
            const float4 B3 = *(const float4*)&s_bc[t][12];
            const float4 C0 = *(const float4*)&s_bc[t][16];
            const float4 C1 = *(const float4*)&s_bc[t][20];
            const float4 C2 = *(const float4*)&s_bc[t][24];
            const float4 C3 = *(const float4*)&s_bc[t][28];
            const float Bs[16] = {B0.x,B0.y,B0.z,B0.w, B1.x,B1.y,B1.z,B1.w,
                                  B2.x,B2.y,B2.z,B2.w, B3.x,B3.y,B3.z,B3.w};
            const float Cs[16] = {C0.x,C0.y,C0.z,C0.w, C1.x,C1.y,C1.z,C1.w,
                                  C2.x,C2.y,C2.z,C2.w, C3.x,C3.y,C3.z,C3.w};
            float y = 0.f;
#pragma unroll
            for (int n = 0; n < 16; ++n) {
                const float e = __expf(dtv * a[n]);
                h[n] = e * h[n] + dtu * Bs[n];
                y += h[n] * Cs[n];
            }
            y += dcoef * uv;
            y *= zv / (1.f + __expf(-zv));
            g_y[(size_t)(base + t) * DIv + d] = y;
        }
        __syncthreads();
    }
}

// ---------------------------------------------------------------------------
// Final: LayerNorm(last token) + head.
// ---------------------------------------------------------------------------
__global__ void __launch_bounds__(256)
final_kernel(const float* __restrict__ ln_g, const float* __restrict__ ln_b,
             const float* __restrict__ head_w, const float* __restrict__ head_b,
             float* __restrict__ out)
{
    __shared__ float red[256];
    const int b = blockIdx.x, tid = threadIdx.x;
    const float v = g_h[((size_t)(b * Tv + (Tv - 1))) * DMv + tid];

    red[tid] = v; __syncthreads();
    for (int s = 128; s > 0; s >>= 1) { if (tid < s) red[tid] += red[tid + s]; __syncthreads(); }
    const float mu = red[0] * (1.f / DMv);
    __syncthreads();

    const float dv = v - mu;
    red[tid] = dv * dv; __syncthreads();
    for (int s = 128; s > 0; s >>= 1) { if (tid < s) red[tid] += red[tid + s]; __syncthreads(); }
    const float var = red[0] * (1.f / DMv);
    __syncthreads();

    const float hn = dv * rsqrtf(var + 1e-5f) * ln_g[tid] + ln_b[tid];
    red[tid] = hn * head_w[tid]; __syncthreads();
    for (int s = 128; s > 0; s >>= 1) { if (tid < s) red[tid] += red[tid + s]; __syncthreads(); }
    if (tid == 0) out[b] = red[0] + head_b[0];
}

// ---------------------------------------------------------------------------
// Host launcher
// ---------------------------------------------------------------------------
extern "C" void kernel_launch(void* const* d_in, const int* in_sizes, int n_in,
                              void* d_out, int out_size)
{
    const float* x      = (const float*)d_in[0];
    const float* proj_w = (const float*)d_in[1];
    const float* proj_b = (const float*)d_in[2];
    const float* ipw    = (const float*)d_in[3];
    const float* cw     = (const float*)d_in[4];
    const float* cb     = (const float*)d_in[5];
    const float* xpw    = (const float*)d_in[6];
    const float* dtw    = (const float*)d_in[7];
    const float* dtb    = (const float*)d_in[8];
    const float* A_log  = (const float*)d_in[9];
    const float* Dp     = (const float*)d_in[10];
    const float* opw    = (const float*)d_in[11];
    const float* ln_g   = (const float*)d_in[12];
    const float* ln_b   = (const float*)d_in[13];
    const float* head_w = (const float*)d_in[14];
    const float* head_b = (const float*)d_in[15];
    float* out = (float*)d_out;

    float *hbuf, *xzbuf, *ybuf, *xcbuf, *xdblbuf;
    __nv_bfloat16 *whi, *wlo;
    cudaGetSymbolAddress((void**)&hbuf,    g_h);
    cudaGetSymbolAddress((void**)&xzbuf,   g_xz);
    cudaGetSymbolAddress((void**)&ybuf,    g_y);
    cudaGetSymbolAddress((void**)&xcbuf,   g_xc);
    cudaGetSymbolAddress((void**)&xdblbuf, g_xdbl);
    cudaGetSymbolAddress((void**)&whi,     g_whi);
    cudaGetSymbolAddress((void**)&wlo,     g_wlo);

    // Launch 1: all weight splits (incl. padded xpw).
    split_all_kernel<<<1680, 256>>>(proj_w, ipw, opw, xpw, whi, wlo);

    dim3 grid_in(2, 128);
    dim3 grid_ip(8, 128);
    dim3 grid_op(2, 128);
    dim3 grid_xp(1, 128);
    dim3 grid_p1(4, 8, 7);
    dim3 grid_p2(4, 8, 8);

    // Launch 2: input projection  h = x @ proj_w^T  [8192,256], K=64
    wgemm_nt_kernel<<<grid_in, 256>>>(x, (const float*)0,
                                      whi + W_PROJ, wlo + W_PROJ,
                                      hbuf, BT, DMv, Fv);

    for (int l = 0; l < Lv; ++l) {
        const size_t ipoff = (size_t)l * 262144;
        const size_t opoff = (size_t)l * 131072;
        const size_t xpoff = (size_t)l * 32768;   // 64*512 per layer
        const float* abias  = (l == 0) ? proj_b : (const float*)0;
        const float* alog_l = A_log + (size_t)l * DIv * Nv;

        // in_proj: xz = (h+bias?) @ ipw^T   [8192,1024], K=256
        wgemm_nt_kernel<<<grid_ip, 256>>>(hbuf, abias,
                                          whi + W_IPW + ipoff, wlo + W_IPW + ipoff,
                                          xzbuf, BT, 2*DIv, DMv);

        // Launch 4 (profiled, l==0): conv + SiLU
        conv_silu_kernel<<<512, 256>>>(cw + (size_t)l * DIv * DCv,
                                       cb + (size_t)l * DIv);

        // x_proj via tensor cores: xdbl = xc @ xpw_pad^T   [8192,64], K=512
        wgemm64_kernel<<<grid_xp, 256>>>(xcbuf,
                                         whi + W_XPW + xpoff, wlo + W_XPW + xpoff,
                                         xdblbuf, DIv);

        // dt_proj + softplus + B/C extraction
        dtproj_bc_kernel<<<512, 256>>>(dtw + (size_t)l * DIv * DTRv,
                                       dtb + (size_t)l * DIv);

        scan_pass1_kernel<<<grid_p1, 128>>>(alog_l);
        scan_pass2_kernel<<<grid_p2, 128>>>(alog_l, Dp + (size_t)l * DIv);

        // out_proj: h = y @ opw^T   [8192,256], K=512
        wgemm_nt_kernel<<<grid_op, 256>>>(ybuf, (const float*)0,
                                          whi + W_OPW + opoff, wlo + W_OPW + opoff,
                                          hbuf, BT, DMv, DIv);
    }

    final_kernel<<<Bv, 256>>>(ln_g, ln_b, head_w, head_b, out);
}

// round 14
// speedup vs baseline: 1.1241x; 1.0208x over previous
#include <cuda_runtime.h>
#include <cuda_bf16.h>
#include <mma.h>
#include <math.h>

using namespace nvcuda;

// ---------------------------------------------------------------------------
// Problem constants
// ---------------------------------------------------------------------------
#define Bv   8
#define Tv   1024
#define Fv   64
#define DMv  256
#define Lv   4
#define DIv  512          // 2*DM
#define Nv   16
#define DCv  4
#define DTRv 16           // DM/16
#define BT   (Bv*Tv)      // 8192
#define NCH  8            // scan chunks
#define CHT  128          // timesteps per chunk

// ---------------------------------------------------------------------------
// Scratch (device globals; no runtime allocation allowed)
// ---------------------------------------------------------------------------
__device__ float g_h   [BT * DMv];
__device__ float g_xz  [BT * (2*DIv)];
__device__ float g_xc  [BT * DIv];
__device__ float g_dt  [BT * DIv];
__device__ float g_BC  [BT * (2*Nv)];
__device__ float g_y   [BT * DIv];

__device__ float g_chP[Bv * DIv * Nv * NCH];
__device__ float g_chH[Bv * DIv * Nv * NCH];

// split-bf16 weights: proj[16384] | ipw[1048576] | opw[524288] | xpw_pad[131072]
#define W_PROJ 0
#define W_IPW  16384
#define W_OPW  1064960
#define W_XPW  1589248
__device__ __nv_bfloat16 g_whi[1720320];
__device__ __nv_bfloat16 g_wlo[1720320];

// ---------------------------------------------------------------------------
// One-shot weight split (proj | ipw | opw | padded xpw).  grid 1680 x 256.
// ---------------------------------------------------------------------------
__global__ void __launch_bounds__(256)
split_all_kernel(const float* __restrict__ proj_w,
                 const float* __restrict__ ipw,
                 const float* __restrict__ opw,
                 const float* __restrict__ xpw,
                 __nv_bfloat16* __restrict__ whi,
                 __nv_bfloat16* __restrict__ wlo)
{
    const int i = blockIdx.x * 256 + threadIdx.x;
    float4 v;
    int dst_el;
    if (i < 4096) {
        v = *(const float4*)(proj_w + i*4);
        dst_el = W_PROJ + i*4;
    } else if (i < 266240) {
        const int j = i - 4096;
        v = *(const float4*)(ipw + (size_t)j*4);
        dst_el = W_IPW + j*4;
    } else if (i < 397312) {
        const int j = i - 266240;
        v = *(const float4*)(opw + (size_t)j*4);
        dst_el = W_OPW + j*4;
    } else if (i < 430080) {
        const int j  = i - 397312;
        const int el = j * 4;
        const int l  = el >> 15;
        const int rm = el & 32767;
        const int o  = rm >> 9;
        const int k  = rm & 511;
        if (o < 48) v = *(const float4*)(xpw + (size_t)l*48*512 + o*512 + k);
        else        { v.x = 0.f; v.y = 0.f; v.z = 0.f; v.w = 0.f; }
        dst_el = W_XPW + el;
    } else return;

    __nv_bfloat16* hi = whi + dst_el;
    __nv_bfloat16* lo = wlo + dst_el;
    __nv_bfloat16 h0 = __float2bfloat16(v.x);
    __nv_bfloat16 h1 = __float2bfloat16(v.y);
    __nv_bfloat16 h2 = __float2bfloat16(v.z);
    __nv_bfloat16 h3 = __float2bfloat16(v.w);
    hi[0] = h0; hi[1] = h1; hi[2] = h2; hi[3] = h3;
    lo[0] = __float2bfloat16(v.x - __bfloat162float(h0));
    lo[1] = __float2bfloat16(v.y - __bfloat162float(h1));
    lo[2] = __float2bfloat16(v.z - __bfloat162float(h2));
    lo[3] = __float2bfloat16(v.w - __bfloat162float(h3));
}

// ---------------------------------------------------------------------------
// Tensor-core GEMM (BN=128, unchanged from R12/R13).
// ---------------------------------------------------------------------------
#define SPAD 40

__global__ void __launch_bounds__(256, 2)
wgemm_nt_kernel(const float* __restrict__ A, const float* __restrict__ Abias,
                const __nv_bfloat16* __restrict__ Whi,
                const __nv_bfloat16* __restrict__ Wlo,
                float* __restrict__ C,
                int M, int N, int K)
{
    __shared__ __align__(16) __nv_bfloat16 Ah[64*SPAD];
    __shared__ __align__(16) __nv_bfloat16 Al[64*SPAD];
    __shared__ __align__(16) __nv_bfloat16 Bh[128*SPAD];
    __shared__ __align__(16) __nv_bfloat16 Bl[128*SPAD];

    const int tid = threadIdx.x;
    const int bm  = blockIdx.y, bn = blockIdx.x;
    const int wid = tid >> 5;
    const int wm  = wid >> 2;
    const int wn  = wid & 3;

    wmma::fragment<wmma::accumulator, 16, 16, 16, float> acc[2][2];
#pragma unroll
    for (int mi = 0; mi < 2; ++mi)
#pragma unroll
        for (int ni = 0; ni < 2; ++ni)
            wmma::fill_fragment(acc[mi][ni], 0.0f);

    for (int k0 = 0; k0 < K; k0 += 32) {
#pragma unroll
        for (int i = 0; i < 2; ++i) {
            const int idx = tid + i * 256;
            const int row = idx >> 3;
            const int kc  = (idx & 7) << 2;
            float4 v = *(const float4*)(A + (size_t)(bm*64 + row) * K + k0 + kc);
            if (Abias) {
                const float4 bb = *(const float4*)(Abias + k0 + kc);
                v.x += bb.x; v.y += bb.y; v.z += bb.z; v.w += bb.w;
            }
            __nv_bfloat16 h0 = __float2bfloat16(v.x);
            __nv_bfloat16 h1 = __float2bfloat16(v.y);
            __nv_bfloat16 h2 = __float2bfloat16(v.z);
            __nv_bfloat16 h3 = __float2bfloat16(v.w);
            __nv_bfloat162 ph0; ph0.x = h0; ph0.y = h1;
            __nv_bfloat162 ph1; ph1.x = h2; ph1.y = h3;
            *(__nv_bfloat162*)(Ah + row*SPAD + kc)     = ph0;
            *(__nv_bfloat162*)(Ah + row*SPAD + kc + 2) = ph1;
            __nv_bfloat162 pl0; pl0.x = __float2bfloat16(v.x - __bfloat162float(h0));
                                pl0.y = __float2bfloat16(v.y - __bfloat162float(h1));
            __nv_bfloat162 pl1; pl1.x = __float2bfloat16(v.z - __bfloat162float(h2));
                                pl1.y = __float2bfloat16(v.w - __bfloat162float(h3));
            *(__nv_bfloat162*)(Al + row*SPAD + kc)     = pl0;
            *(__nv_bfloat162*)(Al + row*SPAD + kc + 2) = pl1;
        }
#pragma unroll
        for (int i = 0; i < 2; ++i) {
            const int idx = tid + i * 256;
            const int row = idx >> 2;
            const int kc  = (idx & 3) << 3;
            const size_t g = (size_t)(bn*128 + row) * K + k0 + kc;
            *(float4*)(Bh + row*SPAD + kc) = *(const float4*)(Whi + g);
            *(float4*)(Bl + row*SPAD + kc) = *(const float4*)(Wlo + g);
        }
        __syncthreads();

#pragma unroll
        for (int ks = 0; ks < 32; ks += 16) {
            wmma::fragment<wmma::matrix_b, 16, 16, 16, __nv_bfloat16, wmma::col_major> bH[2], bL[2];
#pragma unroll
            for (int ni = 0; ni < 2; ++ni) {
                const int rr = wn*32 + ni*16;
                wmma::load_matrix_sync(bH[ni], Bh + rr*SPAD + ks, SPAD);
                wmma::load_matrix_sync(bL[ni], Bl + rr*SPAD + ks, SPAD);
            }
#pragma unroll
            for (int mi = 0; mi < 2; ++mi) {
                wmma::fragment<wmma::matrix_a, 16, 16, 16, __nv_bfloat16, wmma::row_major> aH, aL;
                const int rr = wm*32 + mi*16;
                wmma::load_matrix_sync(aH, Ah + rr*SPAD + ks, SPAD);
                wmma::load_matrix_sync(aL, Al + rr*SPAD + ks, SPAD);
#pragma unroll
                for (int ni = 0; ni < 2; ++ni) {
                    wmma::mma_sync(acc[mi][ni], aH, bH[ni], acc[mi][ni]);
                    wmma::mma_sync(acc[mi][ni], aH, bL[ni], acc[mi][ni]);
                    wmma::mma_sync(acc[mi][ni], aL, bH[ni], acc[mi][ni]);
                }
            }
        }
        __syncthreads();
    }

#pragma unroll
    for (int mi = 0; mi < 2; ++mi)
#pragma unroll
        for (int ni = 0; ni < 2; ++ni) {
            const int rr = bm*64 + wm*32 + mi*16;
            const int cc = bn*128 + wn*32 + ni*16;
            wmma::store_matrix_sync(C + (size_t)rr * N + cc, acc[mi][ni], N,
                                    wmma::mem_row_major);
        }
}

// ---------------------------------------------------------------------------
// conv(4) + bias + SiLU -> g_xc.  1024 blocks (8 timesteps each), 256 thr.
// ---------------------------------------------------------------------------
__global__ void __launch_bounds__(256)
conv_silu_kernel(const float* __restrict__ conv_w,
                 const float* __restrict__ conv_b)
{
    const int blk = blockIdx.x;
    const int b   = blk >> 7;             // 128 chunks per batch
    const int t0  = (blk & 127) << 3;     // 8 timesteps
    const int tid = threadIdx.x;

#pragma unroll
    for (int dd = 0; dd < 2; ++dd) {
        const int d = tid + dd * 256;
        const float* xin = g_xz + (size_t)(b * Tv) * (2*DIv) + d;
        const float4 cw4 = *(const float4*)(conv_w + d*4);
        const float  cb  = conv_b[d];
        float x0 = (t0 - 3 >= 0) ? xin[(size_t)(t0-3) * (2*DIv)] : 0.f;
        float x1 = (t0 - 2 >= 0) ? xin[(size_t)(t0-2) * (2*DIv)] : 0.f;
        float x2 = (t0 - 1 >= 0) ? xin[(size_t)(t0-1) * (2*DIv)] : 0.f;
#pragma unroll
        for (int tt = 0; tt < 8; ++tt) {
            const float x3 = xin[(size_t)(t0+tt) * (2*DIv)];
            float s = cw4.x*x0 + cw4.y*x1 + cw4.z*x2 + cw4.w*x3 + cb;
            g_xc[((size_t)(b*Tv + t0 + tt)) * DIv + d] = s / (1.f + __expf(-s));
            x0 = x1; x1 = x2; x2 = x3;
        }
    }
}

// ---------------------------------------------------------------------------
// Fused x_proj GEMM (BN=64) + dt_proj/softplus + B/C extraction.
// A = g_xc [8192,512]; W = padded xpw hi/lo [64,512].
// Block: 64 rows.  After MMA, xdbl tile goes to smem; the same block then
// computes dt for its 64 rows x 512 channels and writes B/C.
// grid (1, 128), 256 threads.
// ---------------------------------------------------------------------------
__global__ void __launch_bounds__(256, 2)
xproj_dt_kernel(const __nv_bfloat16* __restrict__ Whi,
                const __nv_bfloat16* __restrict__ Wlo,
                const float* __restrict__ dtw,
                const float* __restrict__ dtb)
{
    __shared__ __align__(16) __nv_bfloat16 Ah[64*SPAD];
    __shared__ __align__(16) __nv_bfloat16 Al[64*SPAD];
    __shared__ __align__(16) __nv_bfloat16 Bh[64*SPAD];
    __shared__ __align__(16) __nv_bfloat16 Bl[64*SPAD];
    __shared__ __align__(16) float xdbl_s[64][68];

    const int tid = threadIdx.x;
    const int bm  = blockIdx.y;
    const int wid = tid >> 5;
    const int wm  = wid >> 1;        // 0..3 -> 16 rows each
    const int wn  = wid & 1;         // 0..1 -> 32 cols each
    const int K   = DIv;

    wmma::fragment<wmma::accumulator, 16, 16, 16, float> acc[2];
    wmma::fill_fragment(acc[0], 0.0f);
    wmma::fill_fragment(acc[1], 0.0f);

    for (int k0 = 0; k0 < K; k0 += 32) {
#pragma unroll
        for (int i = 0; i < 2; ++i) {
            const int idx = tid + i * 256;
            const int row = idx >> 3;
            const int kc  = (idx & 7) << 2;
            const float4 v = *(const float4*)(g_xc + (size_t)(bm*64 + row) * K + k0 + kc);
            __nv_bfloat16 h0 = __float2bfloat16(v.x);
            __nv_bfloat16 h1 = __float2bfloat16(v.y);
            __nv_bfloat16 h2 = __float2bfloat16(v.z);
            __nv_bfloat16 h3 = __float2bfloat16(v.w);
            __nv_bfloat162 ph0; ph0.x = h0; ph0.y = h1;
            __nv_bfloat162 ph1; ph1.x = h2; ph1.y = h3;
            *(__nv_bfloat162*)(Ah + row*SPAD + kc)     = ph0;
            *(__nv_bfloat162*)(Ah + row*SPAD + kc + 2) = ph1;
            __nv_bfloat162 pl0; pl0.x = __float2bfloat16(v.x - __bfloat162float(h0));
                                pl0.y = __float2bfloat16(v.y - __bfloat162float(h1));
            __nv_bfloat162 pl1; pl1.x = __float2bfloat16(v.z - __bfloat162float(h2));
                                pl1.y = __float2bfloat16(v.w - __bfloat162float(h3));
            *(__nv_bfloat162*)(Al + row*SPAD + kc)     = pl0;
            *(__nv_bfloat162*)(Al + row*SPAD + kc + 2) = pl1;
        }
        {
            const int row = tid >> 2;
            const int kc  = (tid & 3) << 3;
            const size_t g = (size_t)row * K + k0 + kc;
            *(float4*)(Bh + row*SPAD + kc) = *(const float4*)(Whi + g);
            *(float4*)(Bl + row*SPAD + kc) = *(const float4*)(Wlo + g);
        }
        __syncthreads();

#pragma unroll
        for (int ks = 0; ks < 32; ks += 16) {
            wmma::fragment<wmma::matrix_b, 16, 16, 16, __nv_bfloat16, wmma::col_major> bH[2], bL[2];
#pragma unroll
            for (int ni = 0; ni < 2; ++ni) {
                const int rr = wn*32 + ni*16;
                wmma::load_matrix_sync(bH[ni], Bh + rr*SPAD + ks, SPAD);
                wmma::load_matrix_sync(bL[ni], Bl + rr*SPAD + ks, SPAD);
            }
            wmma::fragment<wmma::matrix_a, 16, 16, 16, __nv_bfloat16, wmma::row_major> aH, aL;
            wmma::load_matrix_sync(aH, Ah + (wm*16)*SPAD + ks, SPAD);
            wmma::load_matrix_sync(aL, Al + (wm*16)*SPAD + ks, SPAD);
#pragma unroll
            for (int ni = 0; ni < 2; ++ni) {
                wmma::mma_sync(acc[ni], aH, bH[ni], acc[ni]);
                wmma::mma_sync(acc[ni], aH, bL[ni], acc[ni]);
                wmma::mma_sync(acc[ni], aL, bH[ni], acc[ni]);
            }
        }
        __syncthreads();
    }

    // ---- epilogue: xdbl tile into smem -----------------------------------
#pragma unroll
    for (int ni = 0; ni < 2; ++ni)
        wmma::store_matrix_sync(&xdbl_s[wm*16][wn*32 + ni*16], acc[ni], 68,
                                wmma::mem_row_major);
    __syncthreads();

    const int row0 = bm * 64;   // tiles never cross batch boundaries (64|1024)

    // ---- B/C extraction: 64 rows x 32 cols -------------------------------
    {
        int idx = tid;
#pragma unroll
        for (int r = 0; r < 8; ++r, idx += 256) {
            const int tt = idx >> 5, c = idx & 31;
            g_BC[((size_t)(row0 + tt)) * (2*Nv) + c] = xdbl_s[tt][16 + c];
        }
    }

    // ---- dt_proj + softplus: 2 channels/thread across 64 rows ------------
    {
        const int d0 = tid, d1 = tid + 256;
        float w0[16], w1[16];
        *(float4*)&w0[0]  = *(const float4*)(dtw + d0*16 + 0);
        *(float4*)&w0[4]  = *(const float4*)(dtw + d0*16 + 4);
        *(float4*)&w0[8]  = *(const float4*)(dtw + d0*16 + 8);
        *(float4*)&w0[12] = *(const float4*)(dtw + d0*16 + 12);
        *(float4*)&w1[0]  = *(const float4*)(dtw + d1*16 + 0);
        *(float4*)&w1[4]  = *(const float4*)(dtw + d1*16 + 4);
        *(float4*)&w1[8]  = *(const float4*)(dtw + d1*16 + 8);
        *(float4*)&w1[12] = *(const float4*)(dtw + d1*16 + 12);
        const float b0 = dtb[d0], b1 = dtb[d1];

        for (int r = 0; r < 64; ++r) {
            float xv[16];
            *(float4*)&xv[0]  = *(const float4*)&xdbl_s[r][0];
            *(float4*)&xv[4]  = *(const float4*)&xdbl_s[r][4];
            *(float4*)&xv[8]  = *(const float4*)&xdbl_s[r][8];
            *(float4*)&xv[12] = *(const float4*)&xdbl_s[r][12];
            float s0 = b0, s1 = b1;
#pragma unroll
            for (int k = 0; k < 16; ++k) {
                s0 += xv[k] * w0[k];
                s1 += xv[k] * w1[k];
            }
            const float sp0 = fmaxf(s0, 0.f) + log1pf(__expf(-fabsf(s0)));
            const float sp1 = fmaxf(s1, 0.f) + log1pf(__expf(-fabsf(s1)));
            const size_t o = ((size_t)(row0 + r)) * DIv;
            g_dt[o + d0] = sp0;
            g_dt[o + d1] = sp1;
        }
    }
}

// ---------------------------------------------------------------------------
// Scan v3 pass 1 (unchanged).  grid (4, 8, 7), 128 threads.
// ---------------------------------------------------------------------------
__global__ void __launch_bounds__(128)
scan_pass1_kernel(const float* __restrict__ A_log)
{
    __shared__ __align__(16) float s_b[64][16];

    const int tid = threadIdx.x;
    const int d   = blockIdx.x * 128 + tid;
    const int b   = blockIdx.y;
    const int ch  = blockIdx.z;

    float a[16];
    {
        float4 v0 = *(const float4*)(A_log + d*16 + 0);
        float4 v1 = *(const float4*)(A_log + d*16 + 4);
        float4 v2 = *(const float4*)(A_log + d*16 + 8);
        float4 v3 = *(const float4*)(A_log + d*16 + 12);
        a[0]=-__expf(v0.x); a[1]=-__expf(v0.y); a[2]=-__expf(v0.z); a[3]=-__expf(v0.w);
        a[4]=-__expf(v1.x); a[5]=-__expf(v1.y); a[6]=-__expf(v1.z); a[7]=-__expf(v1.w);
        a[8]=-__expf(v2.x); a[9]=-__expf(v2.y); a[10]=-__expf(v2.z); a[11]=-__expf(v2.w);
        a[12]=-__expf(v3.x); a[13]=-__expf(v3.y); a[14]=-__expf(v3.z); a[15]=-__expf(v3.w);
    }

    float h[16], P[16];
#pragma unroll
    for (int n = 0; n < 16; ++n) { h[n] = 0.f; P[n] = 1.f; }

    for (int sc = 0; sc < 2; ++sc) {
        const int base = b * Tv + ch * CHT + sc * 64;
#pragma unroll
        for (int i = 0; i < 8; ++i) {
            const int idx = tid + i * 128;
            const int t = idx >> 4, n = idx & 15;
            s_b[t][n] = g_BC[(size_t)(base + t) * (2*Nv) + n];
        }
        __syncthreads();

#pragma unroll 2
        for (int t = 0; t < 64; ++t) {
            const float dtv = g_dt[(size_t)(base + t) * DIv + d];
            const float uv  = g_xc[(size_t)(base + t) * DIv + d];
            const float dtu = dtv * uv;
            const float4 B0 = *(const float4*)&s_b[t][0];
            const float4 B1 = *(const float4*)&s_b[t][4];
            const float4 B2 = *(const float4*)&s_b[t][8];
            const float4 B3 = *(const float4*)&s_b[t][12];
            const float Bs[16] = {B0.x,B0.y,B0.z,B0.w, B1.x,B1.y,B1.z,B1.w,
                                  B2.x,B2.y,B2.z,B2.w, B3.x,B3.y,B3.z,B3.w};
#pragma unroll
            for (int n = 0; n < 16; ++n) {
                const float e = __expf(dtv * a[n]);
                h[n] = e * h[n] + dtu * Bs[n];
                P[n] *= e;
            }
        }
        __syncthreads();
    }

    const size_t o = (((size_t)b * DIv + d) * Nv) * NCH + ch;
#pragma unroll
    for (int n = 0; n < 16; ++n) {
        g_chP[o + n*NCH] = P[n];
        g_chH[o + n*NCH] = h[n];
    }
}

// ---------------------------------------------------------------------------
// Scan v3 pass 2 (unchanged).  grid (4, 8, 8), 128 threads.
// ---------------------------------------------------------------------------
__global__ void __launch_bounds__(128)
scan_pass2_kernel(const float* __restrict__ A_log, const float* __restrict__ Dp)
{
    __shared__ __align__(16) float s_bc[64][32];

    const int tid = threadIdx.x;
    const int d   = blockIdx.x * 128 + tid;
    const int b   = blockIdx.y;
    const int ch  = blockIdx.z;

    float a[16];
    {
        float4 v0 = *(const float4*)(A_log + d*16 + 0);
        float4 v1 = *(const float4*)(A_log + d*16 + 4);
        float4 v2 = *(const float4*)(A_log + d*16 + 8);
        float4 v3 = *(const float4*)(A_log + d*16 + 12);
        a[0]=-__expf(v0.x); a[1]=-__expf(v0.y); a[2]=-__expf(v0.z); a[3]=-__expf(v0.w);
        a[4]=-__expf(v1.x); a[5]=-__expf(v1.y); a[6]=-__expf(v1.z); a[7]=-__expf(v1.w);
        a[8]=-__expf(v2.x); a[9]=-__expf(v2.y); a[10]=-__expf(v2.z); a[11]=-__expf(v2.w);
        a[12]=-__expf(v3.x); a[13]=-__expf(v3.y); a[14]=-__expf(v3.z); a[15]=-__expf(v3.w);
    }
    const float dcoef = Dp[d];

    float h[16];
    {
        const size_t sb = (((size_t)b * DIv + d) * Nv) * NCH;
#pragma unroll
        for (int n = 0; n < 16; ++n) {
            float hh = 0.f;
            for (int c = 0; c < ch; ++c)
                hh = g_chP[sb + n*NCH + c] * hh + g_chH[sb + n*NCH + c];
            h[n] = hh;
        }
    }

    for (int sc = 0; sc < 2; ++sc) {
        const int base = b * Tv + ch * CHT + sc * 64;
#pragma unroll
        for (int i = 0; i < 16; ++i) {
            const int idx = tid + i * 128;
            const int t = idx >> 5, c = idx & 31;
            s_bc[t][c] = g_BC[(size_t)(base + t) * (2*Nv) + c];
        }
        __syncthreads();

#pragma unroll 2
        for (int t = 0; t < 64; ++t) {
            const float dtv = g_dt[(size_t)(base + t) * DIv + d];
            const float uv  = g_xc[(size_t)(base + t) * DIv + d];
            const float zv  = g_xz[(size_t)(base + t) * (2*DIv) + DIv + d];
            const float dtu = dtv * uv;
            const float4 B0 = *(const float4*)&s_bc[t][0];
            const float4 B1 = *(const float4*)&s_bc[t][4];
            const float4 B2 = *(const float4*)&s_bc[t][8];
            const float4 B3 = *(const float4*)&s_bc[t][12];
            const float4 C0 = *(const float4*)&s_bc[t][16];
            const float4 C1 = *(const float4*)&s_bc[t][20];
            const float4 C2 = *(const float4*)&s_bc[t][24];
            const float4 C3 = *(const float4*)&s_bc[t][28];
            const float Bs[16] = {B0.x,B0.y,B0.z,B0.w, B1.x,B1.y,B1.z,B1.w,
                                  B2.x,B2.y,B2.z,B2.w, B3.x,B3.y,B3.z,B3.w};
            const float Cs[16] = {C0.x,C0.y,C0.z,C0.w, C1.x,C1.y,C1.z,C1.w,
                                  C2.x,C2.y,C2.z,C2.w, C3.x,C3.y,C3.z,C3.w};
            float y = 0.f;
#pragma unroll
            for (int n = 0; n < 16; ++n) {
                const float e = __expf(dtv * a[n]);
                h[n] = e * h[n] + dtu * Bs[n];
                y += h[n] * Cs[n];
            }
            y += dcoef * uv;
            y *= zv / (1.f + __expf(-zv));
            g_y[(size_t)(base + t) * DIv + d] = y;
        }
        __syncthreads();
    }
}

// ---------------------------------------------------------------------------
// Final: LayerNorm(last token) + head.
// ---------------------------------------------------------------------------
__global__ void __launch_bounds__(256)
final_kernel(const float* __restrict__ ln_g, const float* __restrict__ ln_b,
             const float* __restrict__ head_w, const float* __restrict__ head_b,
             float* __restrict__ out)
{
    __shared__ float red[256];
    const int b = blockIdx.x, tid = threadIdx.x;
    const float v = g_h[((size_t)(b * Tv + (Tv - 1))) * DMv + tid];

    red[tid] = v; __syncthreads();
    for (int s = 128; s > 0; s >>= 1) { if (tid < s) red[tid] += red[tid + s]; __syncthreads(); }
    const float mu = red[0] * (1.f / DMv);
    __syncthreads();

    const float dv = v - mu;
    red[tid] = dv * dv; __syncthreads();
    for (int s = 128; s > 0; s >>= 1) { if (tid < s) red[tid] += red[tid + s]; __syncthreads(); }
    const float var = red[0] * (1.f / DMv);
    __syncthreads();

    const float hn = dv * rsqrtf(var + 1e-5f) * ln_g[tid] + ln_b[tid];
    red[tid] = hn * head_w[tid]; __syncthreads();
    for (int s = 128; s > 0; s >>= 1) { if (tid < s) red[tid] += red[tid + s]; __syncthreads(); }
    if (tid == 0) out[b] = red[0] + head_b[0];
}

// ---------------------------------------------------------------------------
// Host launcher
// ---------------------------------------------------------------------------
extern "C" void kernel_launch(void* const* d_in, const int* in_sizes, int n_in,
                              void* d_out, int out_size)
{
    const float* x      = (const float*)d_in[0];
    const float* proj_w = (const float*)d_in[1];
    const float* proj_b = (const float*)d_in[2];
    const float* ipw    = (const float*)d_in[3];
    const float* cw     = (const float*)d_in[4];
    const float* cb     = (const float*)d_in[5];
    const float* xpw    = (const float*)d_in[6];
    const float* dtw    = (const float*)d_in[7];
    const float* dtb    = (const float*)d_in[8];
    const float* A_log  = (const float*)d_in[9];
    const float* Dp     = (const float*)d_in[10];
    const float* opw    = (const float*)d_in[11];
    const float* ln_g   = (const float*)d_in[12];
    const float* ln_b   = (const float*)d_in[13];
    const float* head_w = (const float*)d_in[14];
    const float* head_b = (const float*)d_in[15];
    float* out = (float*)d_out;

    float *hbuf, *xzbuf, *ybuf;
    __nv_bfloat16 *whi, *wlo;
    cudaGetSymbolAddress((void**)&hbuf,  g_h);
    cudaGetSymbolAddress((void**)&xzbuf, g_xz);
    cudaGetSymbolAddress((void**)&ybuf,  g_y);
    cudaGetSymbolAddress((void**)&whi,   g_whi);
    cudaGetSymbolAddress((void**)&wlo,   g_wlo);

    // Launch 1: all weight splits.
    split_all_kernel<<<1680, 256>>>(proj_w, ipw, opw, xpw, whi, wlo);

    dim3 grid_in(2, 128);
    dim3 grid_ip(8, 128);
    dim3 grid_op(2, 128);
    dim3 grid_xp(1, 128);
    dim3 grid_p1(4, 8, 7);
    dim3 grid_p2(4, 8, 8);

    // Launch 2: input projection  h = x @ proj_w^T  [8192,256], K=64
    wgemm_nt_kernel<<<grid_in, 256>>>(x, (const float*)0,
                                      whi + W_PROJ, wlo + W_PROJ,
                                      hbuf, BT, DMv, Fv);

    for (int l = 0; l < Lv; ++l) {
        const size_t ipoff = (size_t)l * 262144;
        const size_t opoff = (size_t)l * 131072;
        const size_t xpoff = (size_t)l * 32768;
        const float* abias  = (l == 0) ? proj_b : (const float*)0;
        const float* alog_l = A_log + (size_t)l * DIv * Nv;

        // in_proj: xz = (h+bias?) @ ipw^T   [8192,1024], K=256
        wgemm_nt_kernel<<<grid_ip, 256>>>(hbuf, abias,
                                          whi + W_IPW + ipoff, wlo + W_IPW + ipoff,
                                          xzbuf, BT, 2*DIv, DMv);

        // Launch 4 (profiled, l==0): conv + SiLU (1024 blocks)
        conv_silu_kernel<<<1024, 256>>>(cw + (size_t)l * DIv * DCv,
                                        cb + (size_t)l * DIv);

        // fused x_proj GEMM + dt_proj + B/C
        xproj_dt_kernel<<<grid_xp, 256>>>(whi + W_XPW + xpoff,
                                          wlo + W_XPW + xpoff,
                                          dtw + (size_t)l * DIv * DTRv,
                                          dtb + (size_t)l * DIv);

        scan_pass1_kernel<<<grid_p1, 128>>>(alog_l);
        scan_pass2_kernel<<<grid_p2, 128>>>(alog_l, Dp + (size_t)l * DIv);

        // out_proj: h = y @ opw^T   [8192,256], K=512
        wgemm_nt_kernel<<<grid_op, 256>>>(ybuf, (const float*)0,
                                          whi + W_OPW + opoff, wlo + W_OPW + opoff,
                                          hbuf, BT, DMv, DIv);
    }

    final_kernel<<<Bv, 256>>>(ln_g, ln_b, head_w, head_b, out);
}

// round 15
// speedup vs baseline: 1.1452x; 1.0188x over previous
#include <cuda_runtime.h>
#include <cuda_bf16.h>
#include <mma.h>
#include <math.h>

using namespace nvcuda;

// ---------------------------------------------------------------------------
// Problem constants
// ---------------------------------------------------------------------------
#define Bv   8
#define Tv   1024
#define Fv   64
#define DMv  256
#define Lv   4
#define DIv  512          // 2*DM
#define Nv   16
#define DCv  4
#define DTRv 16           // DM/16
#define BT   (Bv*Tv)      // 8192
#define NCH  8            // scan chunks
#define CHT  128          // timesteps per chunk

// ---------------------------------------------------------------------------
// Scratch (device globals; no runtime allocation allowed)
// ---------------------------------------------------------------------------
__device__ float g_h   [BT * DMv];
__device__ float g_xz  [BT * (2*DIv)];
__device__ float g_xc  [BT * DIv];
__device__ float g_dt  [BT * DIv];
__device__ float g_BC  [BT * (2*Nv)];
__device__ float g_y   [BT * DIv];

__device__ float g_chP[Bv * DIv * Nv * NCH];
__device__ float g_chH[Bv * DIv * Nv * NCH];

// split-bf16 weights: proj[16384] | ipw[1048576] | opw[524288] | xpw_pad[131072]
#define W_PROJ 0
#define W_IPW  16384
#define W_OPW  1064960
#define W_XPW  1589248
__device__ __nv_bfloat16 g_whi[1720320];
__device__ __nv_bfloat16 g_wlo[1720320];

// ---------------------------------------------------------------------------
// One-shot weight split (proj | ipw | opw | padded xpw).  grid 1680 x 256.
// ---------------------------------------------------------------------------
__global__ void __launch_bounds__(256)
split_all_kernel(const float* __restrict__ proj_w,
                 const float* __restrict__ ipw,
                 const float* __restrict__ opw,
                 const float* __restrict__ xpw,
                 __nv_bfloat16* __restrict__ whi,
                 __nv_bfloat16* __restrict__ wlo)
{
    const int i = blockIdx.x * 256 + threadIdx.x;
    float4 v;
    int dst_el;
    if (i < 4096) {
        v = *(const float4*)(proj_w + i*4);
        dst_el = W_PROJ + i*4;
    } else if (i < 266240) {
        const int j = i - 4096;
        v = *(const float4*)(ipw + (size_t)j*4);
        dst_el = W_IPW + j*4;
    } else if (i < 397312) {
        const int j = i - 266240;
        v = *(const float4*)(opw + (size_t)j*4);
        dst_el = W_OPW + j*4;
    } else if (i < 430080) {
        const int j  = i - 397312;
        const int el = j * 4;
        const int l  = el >> 15;
        const int rm = el & 32767;
        const int o  = rm >> 9;
        const int k  = rm & 511;
        if (o < 48) v = *(const float4*)(xpw + (size_t)l*48*512 + o*512 + k);
        else        { v.x = 0.f; v.y = 0.f; v.z = 0.f; v.w = 0.f; }
        dst_el = W_XPW + el;
    } else return;

    __nv_bfloat16* hi = whi + dst_el;
    __nv_bfloat16* lo = wlo + dst_el;
    __nv_bfloat16 h0 = __float2bfloat16(v.x);
    __nv_bfloat16 h1 = __float2bfloat16(v.y);
    __nv_bfloat16 h2 = __float2bfloat16(v.z);
    __nv_bfloat16 h3 = __float2bfloat16(v.w);
    hi[0] = h0; hi[1] = h1; hi[2] = h2; hi[3] = h3;
    lo[0] = __float2bfloat16(v.x - __bfloat162float(h0));
    lo[1] = __float2bfloat16(v.y - __bfloat162float(h1));
    lo[2] = __float2bfloat16(v.z - __bfloat162float(h2));
    lo[3] = __float2bfloat16(v.w - __bfloat162float(h3));
}

// ---------------------------------------------------------------------------
// Tensor-core GEMM (BM=64, BN=128) — used for input proj and out_proj.
// ---------------------------------------------------------------------------
#define SPAD 40

__global__ void __launch_bounds__(256, 2)
wgemm_nt_kernel(const float* __restrict__ A, const float* __restrict__ Abias,
                const __nv_bfloat16* __restrict__ Whi,
                const __nv_bfloat16* __restrict__ Wlo,
                float* __restrict__ C,
                int M, int N, int K)
{
    __shared__ __align__(16) __nv_bfloat16 Ah[64*SPAD];
    __shared__ __align__(16) __nv_bfloat16 Al[64*SPAD];
    __shared__ __align__(16) __nv_bfloat16 Bh[128*SPAD];
    __shared__ __align__(16) __nv_bfloat16 Bl[128*SPAD];

    const int tid = threadIdx.x;
    const int bm  = blockIdx.y, bn = blockIdx.x;
    const int wid = tid >> 5;
    const int wm  = wid >> 2;
    const int wn  = wid & 3;

    wmma::fragment<wmma::accumulator, 16, 16, 16, float> acc[2][2];
#pragma unroll
    for (int mi = 0; mi < 2; ++mi)
#pragma unroll
        for (int ni = 0; ni < 2; ++ni)
            wmma::fill_fragment(acc[mi][ni], 0.0f);

    for (int k0 = 0; k0 < K; k0 += 32) {
#pragma unroll
        for (int i = 0; i < 2; ++i) {
            const int idx = tid + i * 256;
            const int row = idx >> 3;
            const int kc  = (idx & 7) << 2;
            float4 v = *(const float4*)(A + (size_t)(bm*64 + row) * K + k0 + kc);
            if (Abias) {
                const float4 bb = *(const float4*)(Abias + k0 + kc);
                v.x += bb.x; v.y += bb.y; v.z += bb.z; v.w += bb.w;
            }
            __nv_bfloat16 h0 = __float2bfloat16(v.x);
            __nv_bfloat16 h1 = __float2bfloat16(v.y);
            __nv_bfloat16 h2 = __float2bfloat16(v.z);
            __nv_bfloat16 h3 = __float2bfloat16(v.w);
            __nv_bfloat162 ph0; ph0.x = h0; ph0.y = h1;
            __nv_bfloat162 ph1; ph1.x = h2; ph1.y = h3;
            *(__nv_bfloat162*)(Ah + row*SPAD + kc)     = ph0;
            *(__nv_bfloat162*)(Ah + row*SPAD + kc + 2) = ph1;
            __nv_bfloat162 pl0; pl0.x = __float2bfloat16(v.x - __bfloat162float(h0));
                                pl0.y = __float2bfloat16(v.y - __bfloat162float(h1));
            __nv_bfloat162 pl1; pl1.x = __float2bfloat16(v.z - __bfloat162float(h2));
                                pl1.y = __float2bfloat16(v.w - __bfloat162float(h3));
            *(__nv_bfloat162*)(Al + row*SPAD + kc)     = pl0;
            *(__nv_bfloat162*)(Al + row*SPAD + kc + 2) = pl1;
        }
#pragma unroll
        for (int i = 0; i < 2; ++i) {
            const int idx = tid + i * 256;
            const int row = idx >> 2;
            const int kc  = (idx & 3) << 3;
            const size_t g = (size_t)(bn*128 + row) * K + k0 + kc;
            *(float4*)(Bh + row*SPAD + kc) = *(const float4*)(Whi + g);
            *(float4*)(Bl + row*SPAD + kc) = *(const float4*)(Wlo + g);
        }
        __syncthreads();

#pragma unroll
        for (int ks = 0; ks < 32; ks += 16) {
            wmma::fragment<wmma::matrix_b, 16, 16, 16, __nv_bfloat16, wmma::col_major> bH[2], bL[2];
#pragma unroll
            for (int ni = 0; ni < 2; ++ni) {
                const int rr = wn*32 + ni*16;
                wmma::load_matrix_sync(bH[ni], Bh + rr*SPAD + ks, SPAD);
                wmma::load_matrix_sync(bL[ni], Bl + rr*SPAD + ks, SPAD);
            }
#pragma unroll
            for (int mi = 0; mi < 2; ++mi) {
                wmma::fragment<wmma::matrix_a, 16, 16, 16, __nv_bfloat16, wmma::row_major> aH, aL;
                const int rr = wm*32 + mi*16;
                wmma::load_matrix_sync(aH, Ah + rr*SPAD + ks, SPAD);
                wmma::load_matrix_sync(aL, Al + rr*SPAD + ks, SPAD);
#pragma unroll
                for (int ni = 0; ni < 2; ++ni) {
                    wmma::mma_sync(acc[mi][ni], aH, bH[ni], acc[mi][ni]);
                    wmma::mma_sync(acc[mi][ni], aH, bL[ni], acc[mi][ni]);
                    wmma::mma_sync(acc[mi][ni], aL, bH[ni], acc[mi][ni]);
                }
            }
        }
        __syncthreads();
    }

#pragma unroll
    for (int mi = 0; mi < 2; ++mi)
#pragma unroll
        for (int ni = 0; ni < 2; ++ni) {
            const int rr = bm*64 + wm*32 + mi*16;
            const int cc = bn*128 + wn*32 + ni*16;
            wmma::store_matrix_sync(C + (size_t)rr * N + cc, acc[mi][ni], N,
                                    wmma::mem_row_major);
        }
}

// ---------------------------------------------------------------------------
// Big-tile GEMM for in_proj: BM=128, BN=128, warps 4(m) x 2(n),
// warp tile 32x64 (2x4 frags).  25% less LDSM traffic per MMA.
// grid (N/128, M/128) = (8, 64).
// ---------------------------------------------------------------------------
__global__ void __launch_bounds__(256, 2)
wgemm_ip_kernel(const float* __restrict__ A, const float* __restrict__ Abias,
                const __nv_bfloat16* __restrict__ Whi,
                const __nv_bfloat16* __restrict__ Wlo,
                float* __restrict__ C,
                int M, int N, int K)
{
    __shared__ __align__(16) __nv_bfloat16 Ah[128*SPAD];
    __shared__ __align__(16) __nv_bfloat16 Al[128*SPAD];
    __shared__ __align__(16) __nv_bfloat16 Bh[128*SPAD];
    __shared__ __align__(16) __nv_bfloat16 Bl[128*SPAD];

    const int tid = threadIdx.x;
    const int bm  = blockIdx.y, bn = blockIdx.x;
    const int wid = tid >> 5;
    const int wm  = wid >> 1;        // 0..3  -> 32 rows each
    const int wn  = wid & 1;         // 0..1  -> 64 cols each

    wmma::fragment<wmma::accumulator, 16, 16, 16, float> acc[2][4];
#pragma unroll
    for (int mi = 0; mi < 2; ++mi)
#pragma unroll
        for (int ni = 0; ni < 4; ++ni)
            wmma::fill_fragment(acc[mi][ni], 0.0f);

    for (int k0 = 0; k0 < K; k0 += 32) {
        // ---- stage A (128 rows x 32 floats -> hi/lo) ------------------------
#pragma unroll
        for (int i = 0; i < 4; ++i) {
            const int idx = tid + i * 256;       // 0..1023 float4s
            const int row = idx >> 3;
            const int kc  = (idx & 7) << 2;
            float4 v = *(const float4*)(A + (size_t)(bm*128 + row) * K + k0 + kc);
            if (Abias) {
                const float4 bb = *(const float4*)(Abias + k0 + kc);
                v.x += bb.x; v.y += bb.y; v.z += bb.z; v.w += bb.w;
            }
            __nv_bfloat16 h0 = __float2bfloat16(v.x);
            __nv_bfloat16 h1 = __float2bfloat16(v.y);
            __nv_bfloat16 h2 = __float2bfloat16(v.z);
            __nv_bfloat16 h3 = __float2bfloat16(v.w);
            __nv_bfloat162 ph0; ph0.x = h0; ph0.y = h1;
            __nv_bfloat162 ph1; ph1.x = h2; ph1.y = h3;
            *(__nv_bfloat162*)(Ah + row*SPAD + kc)     = ph0;
            *(__nv_bfloat162*)(Ah + row*SPAD + kc + 2) = ph1;
            __nv_bfloat162 pl0; pl0.x = __float2bfloat16(v.x - __bfloat162float(h0));
                                pl0.y = __float2bfloat16(v.y - __bfloat162float(h1));
            __nv_bfloat162 pl1; pl1.x = __float2bfloat16(v.z - __bfloat162float(h2));
                                pl1.y = __float2bfloat16(v.w - __bfloat162float(h3));
            *(__nv_bfloat162*)(Al + row*SPAD + kc)     = pl0;
            *(__nv_bfloat162*)(Al + row*SPAD + kc + 2) = pl1;
        }
        // ---- stage W (pre-split bf16) ---------------------------------------
#pragma unroll
        for (int i = 0; i < 2; ++i) {
            const int idx = tid + i * 256;
            const int row = idx >> 2;
            const int kc  = (idx & 3) << 3;
            const size_t g = (size_t)(bn*128 + row) * K + k0 + kc;
            *(float4*)(Bh + row*SPAD + kc) = *(const float4*)(Whi + g);
            *(float4*)(Bl + row*SPAD + kc) = *(const float4*)(Wlo + g);
        }
        __syncthreads();

#pragma unroll
        for (int ks = 0; ks < 32; ks += 16) {
            wmma::fragment<wmma::matrix_a, 16, 16, 16, __nv_bfloat16, wmma::row_major> aH[2], aL[2];
#pragma unroll
            for (int mi = 0; mi < 2; ++mi) {
                const int rr = wm*32 + mi*16;
                wmma::load_matrix_sync(aH[mi], Ah + rr*SPAD + ks, SPAD);
                wmma::load_matrix_sync(aL[mi], Al + rr*SPAD + ks, SPAD);
            }
#pragma unroll
            for (int ni = 0; ni < 4; ++ni) {
                wmma::fragment<wmma::matrix_b, 16, 16, 16, __nv_bfloat16, wmma::col_major> bH, bL;
                const int rr = wn*64 + ni*16;
                wmma::load_matrix_sync(bH, Bh + rr*SPAD + ks, SPAD);
                wmma::load_matrix_sync(bL, Bl + rr*SPAD + ks, SPAD);
#pragma unroll
                for (int mi = 0; mi < 2; ++mi) {
                    wmma::mma_sync(acc[mi][ni], aH[mi], bH, acc[mi][ni]);
                    wmma::mma_sync(acc[mi][ni], aH[mi], bL, acc[mi][ni]);
                    wmma::mma_sync(acc[mi][ni], aL[mi], bH, acc[mi][ni]);
                }
            }
        }
        __syncthreads();
    }

#pragma unroll
    for (int mi = 0; mi < 2; ++mi)
#pragma unroll
        for (int ni = 0; ni < 4; ++ni) {
            const int rr = bm*128 + wm*32 + mi*16;
            const int cc = bn*128 + wn*64 + ni*16;
            wmma::store_matrix_sync(C + (size_t)rr * N + cc, acc[mi][ni], N,
                                    wmma::mem_row_major);
        }
}

// ---------------------------------------------------------------------------
// conv(4) + bias + SiLU v3: smem-staged, coalesced reads.
// Block = (b, 16-timestep chunk).  Stage 19 rows x 512 xc-columns of g_xz
// into smem, compute from smem, write coalesced.  512 blocks, 256 threads.
// ---------------------------------------------------------------------------
__global__ void __launch_bounds__(256)
conv_silu_kernel(const float* __restrict__ conv_w,
                 const float* __restrict__ conv_b)
{
    __shared__ __align__(16) float xs[19][DIv];    // 38 KB

    const int blk = blockIdx.x;
    const int b   = blk >> 6;             // 64 chunks per batch
    const int t0  = (blk & 63) << 4;      // 16 timesteps
    const int tid = threadIdx.x;

    // ---- stage rows t0-3 .. t0+15 (xc half = first 512 cols of xz row) -----
    // 19 rows x 128 float4s = 2432 loads over 256 threads
    for (int idx = tid; idx < 19 * 128; idx += 256) {
        const int r  = idx >> 7;                 // 0..18
        const int c4 = idx & 127;
        const int t  = t0 - 3 + r;
        float4 v;
        if (t >= 0) v = *(const float4*)(g_xz + (size_t)(b*Tv + t) * (2*DIv) + c4*4);
        else        { v.x = 0.f; v.y = 0.f; v.z = 0.f; v.w = 0.f; }
        *(float4*)&xs[r][c4*4] = v;
    }
    __syncthreads();

    // ---- conv from smem: 2 channels per thread ------------------------------
#pragma unroll
    for (int dd = 0; dd < 2; ++dd) {
        const int d = tid + dd * 256;
        const float4 cw4 = *(const float4*)(conv_w + d*4);
        const float  cb  = conv_b[d];
        float x0 = xs[0][d], x1 = xs[1][d], x2 = xs[2][d];
#pragma unroll
        for (int tt = 0; tt < 16; ++tt) {
            const float x3 = xs[tt + 3][d];
            float s = cw4.x*x0 + cw4.y*x1 + cw4.z*x2 + cw4.w*x3 + cb;
            g_xc[((size_t)(b*Tv + t0 + tt)) * DIv + d] = s / (1.f + __expf(-s));
            x0 = x1; x1 = x2; x2 = x3;
        }
    }
}

// ---------------------------------------------------------------------------
// Fused x_proj GEMM (BN=64) + dt_proj/softplus + B/C (unchanged from R14).
// ---------------------------------------------------------------------------
__global__ void __launch_bounds__(256, 2)
xproj_dt_kernel(const __nv_bfloat16* __restrict__ Whi,
                const __nv_bfloat16* __restrict__ Wlo,
                const float* __restrict__ dtw,
                const float* __restrict__ dtb)
{
    __shared__ __align__(16) __nv_bfloat16 Ah[64*SPAD];
    __shared__ __align__(16) __nv_bfloat16 Al[64*SPAD];
    __shared__ __align__(16) __nv_bfloat16 Bh[64*SPAD];
    __shared__ __align__(16) __nv_bfloat16 Bl[64*SPAD];
    __shared__ __align__(16) float xdbl_s[64][68];

    const int tid = threadIdx.x;
    const int bm  = blockIdx.y;
    const int wid = tid >> 5;
    const int wm  = wid >> 1;
    const int wn  = wid & 1;
    const int K   = DIv;

    wmma::fragment<wmma::accumulator, 16, 16, 16, float> acc[2];
    wmma::fill_fragment(acc[0], 0.0f);
    wmma::fill_fragment(acc[1], 0.0f);

    for (int k0 = 0; k0 < K; k0 += 32) {
#pragma unroll
        for (int i = 0; i < 2; ++i) {
            const int idx = tid + i * 256;
            const int row = idx >> 3;
            const int kc  = (idx & 7) << 2;
            const float4 v = *(const float4*)(g_xc + (size_t)(bm*64 + row) * K + k0 + kc);
            __nv_bfloat16 h0 = __float2bfloat16(v.x);
            __nv_bfloat16 h1 = __float2bfloat16(v.y);
            __nv_bfloat16 h2 = __float2bfloat16(v.z);
            __nv_bfloat16 h3 = __float2bfloat16(v.w);
            __nv_bfloat162 ph0; ph0.x = h0; ph0.y = h1;
            __nv_bfloat162 ph1; ph1.x = h2; ph1.y = h3;
            *(__nv_bfloat162*)(Ah + row*SPAD + kc)     = ph0;
            *(__nv_bfloat162*)(Ah + row*SPAD + kc + 2) = ph1;
            __nv_bfloat162 pl0; pl0.x = __float2bfloat16(v.x - __bfloat162float(h0));
                                pl0.y = __float2bfloat16(v.y - __bfloat162float(h1));
            __nv_bfloat162 pl1; pl1.x = __float2bfloat16(v.z - __bfloat162float(h2));
                                pl1.y = __float2bfloat16(v.w - __bfloat162float(h3));
            *(__nv_bfloat162*)(Al + row*SPAD + kc)     = pl0;
            *(__nv_bfloat162*)(Al + row*SPAD + kc + 2) = pl1;
        }
        {
            const int row = tid >> 2;
            const int kc  = (tid & 3) << 3;
            const size_t g = (size_t)row * K + k0 + kc;
            *(float4*)(Bh + row*SPAD + kc) = *(const float4*)(Whi + g);
            *(float4*)(Bl + row*SPAD + kc) = *(const float4*)(Wlo + g);
        }
        __syncthreads();

#pragma unroll
        for (int ks = 0; ks < 32; ks += 16) {
            wmma::fragment<wmma::matrix_b, 16, 16, 16, __nv_bfloat16, wmma::col_major> bH[2], bL[2];
#pragma unroll
            for (int ni = 0; ni < 2; ++ni) {
                const int rr = wn*32 + ni*16;
                wmma::load_matrix_sync(bH[ni], Bh + rr*SPAD + ks, SPAD);
                wmma::load_matrix_sync(bL[ni], Bl + rr*SPAD + ks, SPAD);
            }
            wmma::fragment<wmma::matrix_a, 16, 16, 16, __nv_bfloat16, wmma::row_major> aH, aL;
            wmma::load_matrix_sync(aH, Ah + (wm*16)*SPAD + ks, SPAD);
            wmma::load_matrix_sync(aL, Al + (wm*16)*SPAD + ks, SPAD);
#pragma unroll
            for (int ni = 0; ni < 2; ++ni) {
                wmma::mma_sync(acc[ni], aH, bH[ni], acc[ni]);
                wmma::mma_sync(acc[ni], aH, bL[ni], acc[ni]);
                wmma::mma_sync(acc[ni], aL, bH[ni], acc[ni]);
            }
        }
        __syncthreads();
    }

#pragma unroll
    for (int ni = 0; ni < 2; ++ni)
        wmma::store_matrix_sync(&xdbl_s[wm*16][wn*32 + ni*16], acc[ni], 68,
                                wmma::mem_row_major);
    __syncthreads();

    const int row0 = bm * 64;

    {
        int idx = tid;
#pragma unroll
        for (int r = 0; r < 8; ++r, idx += 256) {
            const int tt = idx >> 5, c = idx & 31;
            g_BC[((size_t)(row0 + tt)) * (2*Nv) + c] = xdbl_s[tt][16 + c];
        }
    }

    {
        const int d0 = tid, d1 = tid + 256;
        float w0[16], w1[16];
        *(float4*)&w0[0]  = *(const float4*)(dtw + d0*16 + 0);
        *(float4*)&w0[4]  = *(const float4*)(dtw + d0*16 + 4);
        *(float4*)&w0[8]  = *(const float4*)(dtw + d0*16 + 8);
        *(float4*)&w0[12] = *(const float4*)(dtw + d0*16 + 12);
        *(float4*)&w1[0]  = *(const float4*)(dtw + d1*16 + 0);
        *(float4*)&w1[4]  = *(const float4*)(dtw + d1*16 + 4);
        *(float4*)&w1[8]  = *(const float4*)(dtw + d1*16 + 8);
        *(float4*)&w1[12] = *(const float4*)(dtw + d1*16 + 12);
        const float b0 = dtb[d0], b1 = dtb[d1];

        for (int r = 0; r < 64; ++r) {
            float xv[16];
            *(float4*)&xv[0]  = *(const float4*)&xdbl_s[r][0];
            *(float4*)&xv[4]  = *(const float4*)&xdbl_s[r][4];
            *(float4*)&xv[8]  = *(const float4*)&xdbl_s[r][8];
            *(float4*)&xv[12] = *(const float4*)&xdbl_s[r][12];
            float s0 = b0, s1 = b1;
#pragma unroll
            for (int k = 0; k < 16; ++k) {
                s0 += xv[k] * w0[k];
                s1 += xv[k] * w1[k];
            }
            const float sp0 = fmaxf(s0, 0.f) + log1pf(__expf(-fabsf(s0)));
            const float sp1 = fmaxf(s1, 0.f) + log1pf(__expf(-fabsf(s1)));
            const size_t o = ((size_t)(row0 + r)) * DIv;
            g_dt[o + d0] = sp0;
            g_dt[o + d1] = sp1;
        }
    }
}

// ---------------------------------------------------------------------------
// Scan v3 pass 1 (unchanged).  grid (4, 8, 7), 128 threads.
// ---------------------------------------------------------------------------
__global__ void __launch_bounds__(128)
scan_pass1_kernel(const float* __restrict__ A_log)
{
    __shared__ __align__(16) float s_b[64][16];

    const int tid = threadIdx.x;
    const int d   = blockIdx.x * 128 + tid;
    const int b   = blockIdx.y;
    const int ch  = blockIdx.z;

    float a[16];
    {
        float4 v0 = *(const float4*)(A_log + d*16 + 0);
        float4 v1 = *(const float4*)(A_log + d*16 + 4);
        float4 v2 = *(const float4*)(A_log + d*16 + 8);
        float4 v3 = *(const float4*)(A_log + d*16 + 12);
        a[0]=-__expf(v0.x); a[1]=-__expf(v0.y); a[2]=-__expf(v0.z); a[3]=-__expf(v0.w);
        a[4]=-__expf(v1.x); a[5]=-__expf(v1.y); a[6]=-__expf(v1.z); a[7]=-__expf(v1.w);
        a[8]=-__expf(v2.x); a[9]=-__expf(v2.y); a[10]=-__expf(v2.z); a[11]=-__expf(v2.w);
        a[12]=-__expf(v3.x); a[13]=-__expf(v3.y); a[14]=-__expf(v3.z); a[15]=-__expf(v3.w);
    }

    float h[16], P[16];
#pragma unroll
    for (int n = 0; n < 16; ++n) { h[n] = 0.f; P[n] = 1.f; }

    for (int sc = 0; sc < 2; ++sc) {
        const int base = b * Tv + ch * CHT + sc * 64;
#pragma unroll
        for (int i = 0; i < 8; ++i) {
            const int idx = tid + i * 128;
            const int t = idx >> 4, n = idx & 15;
            s_b[t][n] = g_BC[(size_t)(base + t) * (2*Nv) + n];
        }
        __syncthreads();

#pragma unroll 2
        for (int t = 0; t < 64; ++t) {
            const float dtv = g_dt[(size_t)(base + t) * DIv + d];
            const float uv  = g_xc[(size_t)(base + t) * DIv + d];
            const float dtu = dtv * uv;
            const float4 B0 = *(const float4*)&s_b[t][0];
            const float4 B1 = *(const float4*)&s_b[t][4];
            const float4 B2 = *(const float4*)&s_b[t][8];
            const float4 B3 = *(const float4*)&s_b[t][12];
            const float Bs[16] = {B0.x,B0.y,B0.z,B0.w, B1.x,B1.y,B1.z,B1.w,
                                  B2.x,B2.y,B2.z,B2.w, B3.x,B3.y,B3.z,B3.w};
#pragma unroll
            for (int n = 0; n < 16; ++n) {
                const float e = __expf(dtv * a[n]);
                h[n] = e * h[n] + dtu * Bs[n];
                P[n] *= e;
            }
        }
        __syncthreads();
    }

    const size_t o = (((size_t)b * DIv + d) * Nv) * NCH + ch;
#pragma unroll
    for (int n = 0; n < 16; ++n) {
        g_chP[o + n*NCH] = P[n];
        g_chH[o + n*NCH] = h[n];
    }
}

// ---------------------------------------------------------------------------
// Scan v3 pass 2 (unchanged).  grid (4, 8, 8), 128 threads.
// ---------------------------------------------------------------------------
__global__ void __launch_bounds__(128)
scan_pass2_kernel(const float* __restrict__ A_log, const float* __restrict__ Dp)
{
    __shared__ __align__(16) float s_bc[64][32];

    const int tid = threadIdx.x;
    const int d   = blockIdx.x * 128 + tid;
    const int b   = blockIdx.y;
    const int ch  = blockIdx.z;

    float a[16];
    {
        float4 v0 = *(const float4*)(A_log + d*16 + 0);
        float4 v1 = *(const float4*)(A_log + d*16 + 4);
        float4 v2 = *(const float4*)(A_log + d*16 + 8);
        float4 v3 = *(const float4*)(A_log + d*16 + 12);
        a[0]=-__expf(v0.x); a[1]=-__expf(v0.y); a[2]=-__expf(v0.z); a[3]=-__expf(v0.w);
        a[4]=-__expf(v1.x); a[5]=-__expf(v1.y); a[6]=-__expf(v1.z); a[7]=-__expf(v1.w);
        a[8]=-__expf(v2.x); a[9]=-__expf(v2.y); a[10]=-__expf(v2.z); a[11]=-__expf(v2.w);
        a[12]=-__expf(v3.x); a[13]=-__expf(v3.y); a[14]=-__expf(v3.z); a[15]=-__expf(v3.w);
    }
    const float dcoef = Dp[d];

    float h[16];
    {
        const size_t sb = (((size_t)b * DIv + d) * Nv) * NCH;
#pragma unroll
        for (int n = 0; n < 16; ++n) {
            float hh = 0.f;
            for (int c = 0; c < ch; ++c)
                hh = g_chP[sb + n*NCH + c] * hh + g_chH[sb + n*NCH + c];
            h[n] = hh;
        }
    }

    for (int sc = 0; sc < 2; ++sc) {
        const int base = b * Tv + ch * CHT + sc * 64;
#pragma unroll
        for (int i = 0; i < 16; ++i) {
            const int idx = tid + i * 128;
            const int t = idx >> 5, c = idx & 31;
            s_bc[t][c] = g_BC[(size_t)(base + t) * (2*Nv) + c];
        }
        __syncthreads();

#pragma unroll 2
        for (int t = 0; t < 64; ++t) {
            const float dtv = g_dt[(size_t)(base + t) * DIv + d];
            const float uv  = g_xc[(size_t)(base + t) * DIv + d];
            const float zv  = g_xz[(size_t)(base + t) * (2*DIv) + DIv + d];
            const float dtu = dtv * uv;
            const float4 B0 = *(const float4*)&s_bc[t][0];
            const float4 B1 = *(const float4*)&s_bc[t][4];
            const float4 B2 = *(const float4*)&s_bc[t][8];
            const float4 B3 = *(const float4*)&s_bc[t][12];
            const float4 C0 = *(const float4*)&s_bc[t][16];
            const float4 C1 = *(const float4*)&s_bc[t][20];
            const float4 C2 = *(const float4*)&s_bc[t][24];
            const float4 C3 = *(const float4*)&s_bc[t][28];
            const float Bs[16] = {B0.x,B0.y,B0.z,B0.w, B1.x,B1.y,B1.z,B1.w,
                                  B2.x,B2.y,B2.z,B2.w, B3.x,B3.y,B3.z,B3.w};
            const float Cs[16] = {C0.x,C0.y,C0.z,C0.w, C1.x,C1.y,C1.z,C1.w,
                                  C2.x,C2.y,C2.z,C2.w, C3.x,C3.y,C3.z,C3.w};
            float y = 0.f;
#pragma unroll
            for (int n = 0; n < 16; ++n) {
                const float e = __expf(dtv * a[n]);
                h[n] = e * h[n] + dtu * Bs[n];
                y += h[n] * Cs[n];
            }
            y += dcoef * uv;
            y *= zv / (1.f + __expf(-zv));
            g_y[(size_t)(base + t) * DIv + d] = y;
        }
        __syncthreads();
    }
}

// ---------------------------------------------------------------------------
// Final: LayerNorm(last token) + head.
// ---------------------------------------------------------------------------
__global__ void __launch_bounds__(256)
final_kernel(const float* __restrict__ ln_g, const float* __restrict__ ln_b,
             const float* __restrict__ head_w, const float* __restrict__ head_b,
             float* __restrict__ out)
{
    __shared__ float red[256];
    const int b = blockIdx.x, tid = threadIdx.x;
    const float v = g_h[((size_t)(b * Tv + (Tv - 1))) * DMv + tid];

    red[tid] = v; __syncthreads();
    for (int s = 128; s > 0; s >>= 1) { if (tid < s) red[tid] += red[tid + s]; __syncthreads(); }
    const float mu = red[0] * (1.f / DMv);
    __syncthreads();

    const float dv = v - mu;
    red[tid] = dv * dv; __syncthreads();
    for (int s = 128; s > 0; s >>= 1) { if (tid < s) red[tid] += red[tid + s]; __syncthreads(); }
    const float var = red[0] * (1.f / DMv);
    __syncthreads();

    const float hn = dv * rsqrtf(var + 1e-5f) * ln_g[tid] + ln_b[tid];
    red[tid] = hn * head_w[tid]; __syncthreads();
    for (int s = 128; s > 0; s >>= 1) { if (tid < s) red[tid] += red[tid + s]; __syncthreads(); }
    if (tid == 0) out[b] = red[0] + head_b[0];
}

// ---------------------------------------------------------------------------
// Host launcher
// ---------------------------------------------------------------------------
extern "C" void kernel_launch(void* const* d_in, const int* in_sizes, int n_in,
                              void* d_out, int out_size)
{
    const float* x      = (const float*)d_in[0];
    const float* proj_w = (const float*)d_in[1];
    const float* proj_b = (const float*)d_in[2];
    const float* ipw    = (const float*)d_in[3];
    const float* cw     = (const float*)d_in[4];
    const float* cb     = (const float*)d_in[5];
    const float* xpw    = (const float*)d_in[6];
    const float* dtw    = (const float*)d_in[7];
    const float* dtb    = (const float*)d_in[8];
    const float* A_log  = (const float*)d_in[9];
    const float* Dp     = (const float*)d_in[10];
    const float* opw    = (const float*)d_in[11];
    const float* ln_g   = (const float*)d_in[12];
    const float* ln_b   = (const float*)d_in[13];
    const float* head_w = (const float*)d_in[14];
    const float* head_b = (const float*)d_in[15];
    float* out = (float*)d_out;

    float *hbuf, *xzbuf, *ybuf;
    __nv_bfloat16 *whi, *wlo;
    cudaGetSymbolAddress((void**)&hbuf,  g_h);
    cudaGetSymbolAddress((void**)&xzbuf, g_xz);
    cudaGetSymbolAddress((void**)&ybuf,  g_y);
    cudaGetSymbolAddress((void**)&whi,   g_whi);
    cudaGetSymbolAddress((void**)&wlo,   g_wlo);

    // Launch 1: all weight splits.
    split_all_kernel<<<1680, 256>>>(proj_w, ipw, opw, xpw, whi, wlo);

    dim3 grid_in(2, 128);     // BM=64 kernel
    dim3 grid_ip(8, 64);      // BM=128 kernel: N=1024/128, M=8192/128
    dim3 grid_op(2, 128);
    dim3 grid_xp(1, 128);
    dim3 grid_p1(4, 8, 7);
    dim3 grid_p2(4, 8, 8);

    // Launch 2: input projection  h = x @ proj_w^T  [8192,256], K=64
    wgemm_nt_kernel<<<grid_in, 256>>>(x, (const float*)0,
                                      whi + W_PROJ, wlo + W_PROJ,
                                      hbuf, BT, DMv, Fv);

    for (int l = 0; l < Lv; ++l) {
        const size_t ipoff = (size_t)l * 262144;
        const size_t opoff = (size_t)l * 131072;
        const size_t xpoff = (size_t)l * 32768;
        const float* abias  = (l == 0) ? proj_b : (const float*)0;
        const float* alog_l = A_log + (size_t)l * DIv * Nv;

        // in_proj (big-tile): xz = (h+bias?) @ ipw^T  [8192,1024], K=256
        wgemm_ip_kernel<<<grid_ip, 256>>>(hbuf, abias,
                                          whi + W_IPW + ipoff, wlo + W_IPW + ipoff,
                                          xzbuf, BT, 2*DIv, DMv);

        // Launch 4 (profiled, l==0): conv + SiLU v3
        conv_silu_kernel<<<512, 256>>>(cw + (size_t)l * DIv * DCv,
                                       cb + (size_t)l * DIv);

        xproj_dt_kernel<<<grid_xp, 256>>>(whi + W_XPW + xpoff,
                                          wlo + W_XPW + xpoff,
                                          dtw + (size_t)l * DIv * DTRv,
                                          dtb + (size_t)l * DIv);

        scan_pass1_kernel<<<grid_p1, 128>>>(alog_l);
        scan_pass2_kernel<<<grid_p2, 128>>>(alog_l, Dp + (size_t)l * DIv);

        // out_proj: h = y @ opw^T   [8192,256], K=512
        wgemm_nt_kernel<<<grid_op, 256>>>(ybuf, (const float*)0,
                                          whi + W_OPW + opoff, wlo + W_OPW + opoff,
                                          hbuf, BT, DMv, DIv);
    }

    final_kernel<<<Bv, 256>>>(ln_g, ln_b, head_w, head_b, out);
}